// round 1
// baseline (speedup 1.0000x reference)
#include <cuda_runtime.h>
#include <math.h>

#define B_    64
#define T_    1024
#define D_    512
#define KTAP  5
#define U_    256
#define G4_   1024            // 4*U
#define TP_   (T_ + 4)        // padded time (2 halo each side)
#define XPD_  (TP_ * D_)      // per-batch padded plane
#define RNN_CTAS 64           // CTAs per direction

// ---------------- scratch (static device globals; no allocation) ----------------
__device__ float g_xp0[(size_t)B_ * XPD_];
__device__ float g_xp1[(size_t)B_ * XPD_];
__device__ float g_pre_f[(size_t)T_ * B_ * G4_];
__device__ float g_pre_b[(size_t)T_ * B_ * G4_];
__device__ float g_h[2][2][B_ * U_];   // [dir][slot][b*U+u]
__device__ unsigned g_bar[2];

// ---------------- init: zero halos, h slots, barrier counters ----------------
__global__ void init_kernel() {
    int idx = blockIdx.x * blockDim.x + threadIdx.x;
    int nh = B_ * 4 * D_;                       // 4 halo rows per batch
    if (idx < nh) {
        int b = idx / (4 * D_);
        int r = (idx / D_) & 3;
        int d = idx % D_;
        int row = (r < 2) ? r : (TP_ - 4 + r);  // rows 0,1,TP-2,TP-1
        g_xp0[(size_t)b * XPD_ + (size_t)row * D_ + d] = 0.f;
        g_xp1[(size_t)b * XPD_ + (size_t)row * D_ + d] = 0.f;
    }
    if (idx < 2 * 2 * B_ * U_) ((float*)g_h)[idx] = 0.f;
    if (idx < 2) g_bar[idx] = 0u;
}

// ---------------- pad-copy input into g_xp0 interior ----------------
__global__ void pad_copy(const float* __restrict__ in) {
    size_t total = (size_t)B_ * T_ * D_;
    for (size_t idx = (size_t)blockIdx.x * blockDim.x + threadIdx.x;
         idx < total; idx += (size_t)gridDim.x * blockDim.x) {
        size_t b = idx / ((size_t)T_ * D_);
        size_t r = idx % ((size_t)T_ * D_);
        size_t t = r / D_;
        size_t d = r % D_;
        g_xp0[b * XPD_ + (t + 2) * D_ + d] = in[idx];
    }
}

// ---------------- SGEMM: 128x128x8, 8x8 microtile, 256 threads ----------------
// A viewed as [rows=t (per batch), kk = tap*512 + din], read from a padded plane.
// B is row-major [KKtot x N] (exactly the conv-weight / lstm-kernel layouts).
// MODE 0: conv epilogue (+bias, BN, ReLU) -> write padded next buffer
// MODE 1: lstm-pre fw: +bias -> C[(t*B + b)*G4 + n]
// MODE 2: lstm-pre bw: +bias -> C[((T-1-t)*B + b)*G4 + n]
#define BM 128
#define BN 128
#define BK 8

template <int MODE>
__global__ __launch_bounds__(256) void gemm_kernel(
    const float* __restrict__ Abase,   // padded plane base (interior offset folded in by caller)
    const float* __restrict__ Bmat,    // [KKtot x N] row-major
    int N, int KKtot,
    const float* __restrict__ bias,
    const float* __restrict__ bng, const float* __restrict__ bnb,
    const float* __restrict__ bnm, const float* __restrict__ bnv,
    float* __restrict__ C)
{
    __shared__ float As[BK][BM + 4];
    __shared__ float Bs[BK][BN];

    const int b  = blockIdx.z;
    const int t0 = blockIdx.y * BM;
    const int n0 = blockIdx.x * BN;
    const float* A = Abase + (size_t)b * XPD_;

    const int tid = threadIdx.x;
    const int tx = tid & 15;         // 0..15 -> n
    const int ty = tid >> 4;         // 0..15 -> m

    const int arow = tid >> 1;       // 0..127
    const int acol = (tid & 1) * 4;  // 0 or 4 (k within tile)
    const int brow = tid >> 5;       // 0..7
    const int bcol = (tid & 31) * 4; // 0..124

    float acc[8][8];
#pragma unroll
    for (int i = 0; i < 8; i++)
#pragma unroll
        for (int j = 0; j < 8; j++) acc[i][j] = 0.f;

    // prefetch first tile
    int tap = 0, d0 = 0;
    float4 av = *(const float4*)&A[(size_t)(t0 + arow + tap) * D_ + d0 + acol];
    float4 bv = *(const float4*)&Bmat[(size_t)(0 + brow) * N + n0 + bcol];

    for (int kk0 = 0; kk0 < KKtot; kk0 += BK) {
        __syncthreads();
        // store current tile
        As[acol + 0][arow] = av.x;
        As[acol + 1][arow] = av.y;
        As[acol + 2][arow] = av.z;
        As[acol + 3][arow] = av.w;
        *(float4*)&Bs[brow][bcol] = bv;
        __syncthreads();

        // prefetch next tile (hidden under compute)
        int nk = kk0 + BK;
        if (nk < KKtot) {
            tap = nk >> 9;          // nk / 512
            d0  = nk & 511;
            av = *(const float4*)&A[(size_t)(t0 + arow + tap) * D_ + d0 + acol];
            bv = *(const float4*)&Bmat[(size_t)nk * N + (size_t)brow * N + n0 + bcol];
        }

#pragma unroll
        for (int k = 0; k < BK; k++) {
            float ar[8], br[8];
#pragma unroll
            for (int i = 0; i < 8; i++) ar[i] = As[k][ty * 8 + i];
#pragma unroll
            for (int j = 0; j < 8; j++) br[j] = Bs[k][tx * 8 + j];
#pragma unroll
            for (int i = 0; i < 8; i++)
#pragma unroll
                for (int j = 0; j < 8; j++) acc[i][j] += ar[i] * br[j];
        }
    }

    // epilogue
#pragma unroll
    for (int i = 0; i < 8; i++) {
        int t = t0 + ty * 8 + i;
#pragma unroll
        for (int j = 0; j < 8; j++) {
            int n = n0 + tx * 8 + j;
            float v = acc[i][j] + __ldg(&bias[n]);
            if (MODE == 0) {
                float inv = rsqrtf(__ldg(&bnv[n]) + 1e-3f);
                v = __ldg(&bng[n]) * (v - __ldg(&bnm[n])) * inv + __ldg(&bnb[n]);
                v = fmaxf(v, 0.f);
                C[(size_t)b * XPD_ + (size_t)(t + 2) * D_ + n] = v;
            } else if (MODE == 1) {
                C[((size_t)t * B_ + b) * G4_ + n] = v;
            } else {
                C[((size_t)(T_ - 1 - t) * B_ + b) * G4_ + n] = v;
            }
        }
    }
}

// ---------------- persistent bi-LSTM recurrence ----------------
// 128 CTAs: dir = bx/64, each CTA owns 4 units. Thread (b=tid>>2, q=tid&3)
// computes i,f,g,o for (b, u0+q). Global h double-buffered + per-dir barrier.
__global__ __launch_bounds__(256) void lstm_kernel(
    const float* __restrict__ pre_f, const float* __restrict__ pre_b,
    const float* __restrict__ wr_f,  const float* __restrict__ wr_b,
    float* __restrict__ out)
{
    extern __shared__ float sm[];
    float* sW = sm;            // [256][16] : k*16 + q*4 + gate
    float* sH = sm + 4096;     // [64][260] padded

    const int bx  = blockIdx.x;
    const int dir = bx >> 6;
    const int u0  = (bx & 63) << 2;
    const float* pre = dir ? pre_b : pre_f;
    const float* Wr  = dir ? wr_b  : wr_f;   // [256 x 1024], gate-major cols
    unsigned* bar = &g_bar[dir];

    const int tid = threadIdx.x;
    const int b = tid >> 2, q = tid & 3, u = u0 + q;

    for (int idx = tid; idx < 4096; idx += 256) {
        int k = idx >> 4, r = idx & 15, qq = r >> 2, g = r & 3;
        sW[idx] = Wr[(size_t)k * G4_ + g * U_ + u0 + qq];
    }

    float c = 0.f;
    float* h0 = &g_h[dir][0][0];
    float* h1 = &g_h[dir][1][0];
    __syncthreads();

    for (int t = 0; t < T_; t++) {
        const float* hr = ((t + 1) & 1) ? h1 : h0;   // h[t-1]; slot 1 zeroed for t=0
        // stage h into smem (bypass L1: other SMs wrote it)
        for (int idx = tid * 4; idx < B_ * U_; idx += 1024) {
            float4 v = __ldcg((const float4*)(hr + idx));
            int row = idx >> 8, col = idx & 255;
            *(float4*)&sH[row * 260 + col] = v;
        }
        __syncthreads();

        const float* p = pre + ((size_t)t * B_ + b) * G4_ + u;
        float z0 = p[0], z1 = p[U_], z2 = p[2 * U_], z3 = p[3 * U_];
        const float* hrow = &sH[b * 260];
#pragma unroll 8
        for (int k = 0; k < U_; k++) {
            float hv = hrow[k];
            float4 w = *(const float4*)&sW[k * 16 + q * 4];
            z0 += hv * w.x;
            z1 += hv * w.y;
            z2 += hv * w.z;
            z3 += hv * w.w;
        }
        float ig = 1.f / (1.f + __expf(-z0));
        float fg = 1.f / (1.f + __expf(-z1));
        float gg = tanhf(z2);
        float og = 1.f / (1.f + __expf(-z3));
        c = fg * c + ig * gg;
        float h = og * tanhf(c);

        float* hw = (t & 1) ? h1 : h0;
        hw[b * U_ + u] = h;
        int tout = dir ? (T_ - 1 - t) : t;
        out[((size_t)b * T_ + tout) * (2 * U_) + dir * U_ + u] = h;

        __syncthreads();                 // all writes of this CTA done
        if (tid == 0) {
            __threadfence();             // release h to gpu scope
            atomicAdd(bar, 1u);
            unsigned target = (unsigned)(t + 1) * RNN_CTAS;
            unsigned v;
            do {
                asm volatile("ld.global.acquire.gpu.u32 %0, [%1];" : "=r"(v) : "l"(bar));
            } while (v < target);
        }
        __syncthreads();
    }
}

// ---------------- launcher ----------------
extern "C" void kernel_launch(void* const* d_in, const int* in_sizes, int n_in,
                              void* d_out, int out_size)
{
    const float* inputs = (const float*)d_in[0];
    const float* convk  = (const float*)d_in[1];
    const float* convb  = (const float*)d_in[2];
    const float* bng    = (const float*)d_in[3];
    const float* bnb    = (const float*)d_in[4];
    const float* bnm    = (const float*)d_in[5];
    const float* bnv    = (const float*)d_in[6];
    const float* wk_f   = (const float*)d_in[7];
    const float* wr_f   = (const float*)d_in[8];
    const float* bi_f   = (const float*)d_in[9];
    const float* wk_b   = (const float*)d_in[10];
    const float* wr_b   = (const float*)d_in[11];
    const float* bi_b   = (const float*)d_in[12];
    float* out = (float*)d_out;

    float *xp0, *xp1, *pre_f, *pre_b;
    cudaGetSymbolAddress((void**)&xp0,   g_xp0);
    cudaGetSymbolAddress((void**)&xp1,   g_xp1);
    cudaGetSymbolAddress((void**)&pre_f, g_pre_f);
    cudaGetSymbolAddress((void**)&pre_b, g_pre_b);

    init_kernel<<<512, 256>>>();
    pad_copy<<<8192, 256>>>(inputs);

    dim3 gc(D_ / BN, T_ / BM, B_);   // (4, 8, 64)
    const size_t wstep = (size_t)KTAP * D_ * D_;
    // conv 0: xp0 -> xp1
    gemm_kernel<0><<<gc, 256>>>(xp0, convk + 0 * wstep, D_, KTAP * D_,
                                convb + 0 * D_, bng + 0 * D_, bnb + 0 * D_,
                                bnm + 0 * D_, bnv + 0 * D_, xp1);
    // conv 1: xp1 -> xp0
    gemm_kernel<0><<<gc, 256>>>(xp1, convk + 1 * wstep, D_, KTAP * D_,
                                convb + 1 * D_, bng + 1 * D_, bnb + 1 * D_,
                                bnm + 1 * D_, bnv + 1 * D_, xp0);
    // conv 2: xp0 -> xp1
    gemm_kernel<0><<<gc, 256>>>(xp0, convk + 2 * wstep, D_, KTAP * D_,
                                convb + 2 * D_, bng + 2 * D_, bnb + 2 * D_,
                                bnm + 2 * D_, bnv + 2 * D_, xp1);

    // LSTM input GEMMs (A = final conv output = xp1 interior)
    dim3 gl(G4_ / BN, T_ / BM, B_);  // (8, 8, 64)
    gemm_kernel<1><<<gl, 256>>>(xp1 + 2 * D_, wk_f, G4_, D_,
                                bi_f, bng, bnb, bnm, bnv, pre_f);
    gemm_kernel<2><<<gl, 256>>>(xp1 + 2 * D_, wk_b, G4_, D_,
                                bi_b, bng, bnb, bnm, bnv, pre_b);

    // recurrence
    const int lstm_smem = (4096 + 64 * 260) * (int)sizeof(float);  // 82944 B
    cudaFuncSetAttribute(lstm_kernel, cudaFuncAttributeMaxDynamicSharedMemorySize, lstm_smem);
    lstm_kernel<<<2 * RNN_CTAS, 256, lstm_smem>>>(pre_f, pre_b, wr_f, wr_b, out);
}

// round 3
// speedup vs baseline: 1.4252x; 1.4252x over previous
#include <cuda_runtime.h>
#include <cuda_bf16.h>
#include <cstdint>
#include <math.h>

#define B_    64
#define T_    1024
#define D_    512
#define KTAP  5
#define U_    256
#define G4_   1024
#define TP_   (T_ + 4)
#define XPD_  (TP_ * D_)
#define RNN_CTAS 64

#define BM    128
#define BN    128
#define KC    32                 // bf16 k per chunk
#define ROWB  80                 // smem row stride (bytes) -> conflict-free ldmatrix
#define TILEB (128 * ROWB)       // 10240 B per tile
#define STAGEB (4 * TILEB)       // AH, AL, BH, BL
#define GSMEM (2 * STAGEB + 256)

// ---------------- scratch ----------------
__device__ uint32_t g_xp0p[(size_t)B_ * XPD_];     // packed hi/lo bf16 planes
__device__ uint32_t g_xp1p[(size_t)B_ * XPD_];
__device__ uint32_t g_wtc[(size_t)3 * 512 * 2560]; // conv weights [i][n][kk] packed
__device__ uint32_t g_wtl[(size_t)2 * 1024 * 512]; // lstm kernels [dir][n][d] packed
__device__ float    g_pre_f[(size_t)T_ * B_ * G4_];
__device__ float    g_pre_b[(size_t)T_ * B_ * G4_];
__device__ float    g_h[2][2][B_ * U_];
__device__ unsigned g_bar[2];

// ---------------- helpers ----------------
__device__ __forceinline__ uint32_t smem_u32(const void* p) {
    uint32_t a;
    asm("{ .reg .u64 t; cvta.to.shared.u64 t, %1; cvt.u32.u64 %0, t; }" : "=r"(a) : "l"(p));
    return a;
}
__device__ __forceinline__ uint32_t pack_hl(float v) {
    __nv_bfloat16 h = __float2bfloat16(v);
    float hf = __bfloat162float(h);
    __nv_bfloat16 l = __float2bfloat16(v - hf);
    return ((uint32_t)__bfloat16_as_ushort(h) << 16) | (uint32_t)__bfloat16_as_ushort(l);
}
#define LDM_X4(R0, R1, R2, R3, ADDR)                                            \
    asm volatile("ldmatrix.sync.aligned.m8n8.x4.shared.b16 {%0,%1,%2,%3}, [%4];"\
        : "=r"(R0), "=r"(R1), "=r"(R2), "=r"(R3) : "r"(ADDR))
__device__ __forceinline__ void mma_bf16(float* c, const uint32_t* a, const uint32_t* b) {
    asm volatile(
        "mma.sync.aligned.m16n8k16.row.col.f32.bf16.bf16.f32 "
        "{%0,%1,%2,%3}, {%4,%5,%6,%7}, {%8,%9}, {%0,%1,%2,%3};"
        : "+f"(c[0]), "+f"(c[1]), "+f"(c[2]), "+f"(c[3])
        : "r"(a[0]), "r"(a[1]), "r"(a[2]), "r"(a[3]), "r"(b[0]), "r"(b[1]));
}

// ---------------- init ----------------
__global__ void init_kernel() {
    int idx = blockIdx.x * blockDim.x + threadIdx.x;
    int nh = B_ * 4 * D_;
    if (idx < nh) {
        int b = idx / (4 * D_);
        int r = (idx / D_) & 3;
        int d = idx % D_;
        int row = (r < 2) ? r : (TP_ - 4 + r);
        g_xp0p[(size_t)b * XPD_ + (size_t)row * D_ + d] = 0u;
        g_xp1p[(size_t)b * XPD_ + (size_t)row * D_ + d] = 0u;
    }
    if (idx < 2 * 2 * B_ * U_) ((float*)g_h)[idx] = 0.f;
    if (idx < 2) g_bar[idx] = 0u;
}

// ---------------- pack input ----------------
__global__ void pad_pack(const float* __restrict__ in) {
    size_t total = (size_t)B_ * T_ * D_;
    for (size_t idx = (size_t)blockIdx.x * blockDim.x + threadIdx.x;
         idx < total; idx += (size_t)gridDim.x * blockDim.x) {
        size_t b = idx / ((size_t)T_ * D_);
        size_t r = idx % ((size_t)T_ * D_);
        size_t t = r / D_, d = r % D_;
        g_xp0p[b * XPD_ + (t + 2) * D_ + d] = pack_hl(in[idx]);
    }
}

// ---------------- transpose + split weights ----------------
__global__ void wprep(const float* __restrict__ convk,
                      const float* __restrict__ wkf, const float* __restrict__ wkb) {
    const size_t CONVN = (size_t)3 * 512 * 2560;
    const size_t LSTMN = (size_t)1024 * 512;
    size_t total = CONVN + 2 * LSTMN;
    for (size_t idx = (size_t)blockIdx.x * blockDim.x + threadIdx.x;
         idx < total; idx += (size_t)gridDim.x * blockDim.x) {
        if (idx < CONVN) {
            size_t i = idx / ((size_t)512 * 2560);
            size_t r = idx % ((size_t)512 * 2560);
            size_t n = r / 2560, kk = r % 2560;
            size_t tap = kk >> 9, din = kk & 511;
            g_wtc[idx] = pack_hl(convk[(((i * KTAP + tap) * D_) + din) * D_ + n]);
        } else if (idx < CONVN + LSTMN) {
            size_t j = idx - CONVN;
            size_t n = j >> 9, d = j & 511;
            g_wtl[j] = pack_hl(wkf[d * G4_ + n]);
        } else {
            size_t j = idx - CONVN - LSTMN;
            size_t n = j >> 9, d = j & 511;
            g_wtl[LSTMN + j] = pack_hl(wkb[d * G4_ + n]);
        }
    }
}

// ---------------- warp-MMA split-bf16 GEMM ----------------
// A: packed plane, logical [t][kk] per batch, kk = tap*512 + din
// B: packed [n][KKtot]
// MODE 0: conv (bias, BN, ReLU) -> packed plane interior
// MODE 1/2: lstm pre (+bias) -> fp32 [(t or T-1-t)*B + b][G4]
template <int MODE>
__global__ __launch_bounds__(256, 1) void mma_gemm(
    const uint32_t* __restrict__ Ap, const uint32_t* __restrict__ Bt,
    int KKtot,
    const float* __restrict__ bias,
    const float* __restrict__ bng, const float* __restrict__ bnb,
    const float* __restrict__ bnm, const float* __restrict__ bnv,
    void* __restrict__ Cout)
{
    extern __shared__ char smraw[];
    const uint32_t sbase = smem_u32(smraw);

    const int tid = threadIdx.x;
    const int wid = tid >> 5, lane = tid & 31;
    const int bz = blockIdx.z;
    const int t0 = blockIdx.y * BM;
    const int n0 = blockIdx.x * BN;
    const int wm = wid & 1;      // row group: wm*64
    const int wn = wid >> 1;     // col group: wn*32

    // loader mapping: row lr, 16 packed cols starting lc
    const int lr = tid >> 1;
    const int lc = (tid & 1) << 4;
    char* stp_base = smraw + lr * ROWB + lc * 2;

    // ldmatrix per-lane offsets
    const uint32_t a_off = (uint32_t)((wm * 64 + (lane & 15)) * ROWB + (lane >> 4) * 16);
    const uint32_t b_off = (uint32_t)((wn * 32 + (lane & 7) + ((lane >> 4) << 3)) * ROWB
                                      + ((lane >> 3) & 1) * 16);

    const uint32_t* Abat = Ap + (size_t)bz * XPD_;
    const int NCH = KKtot / KC;

    float cacc[4][4][4];
#pragma unroll
    for (int i = 0; i < 4; i++)
#pragma unroll
        for (int j = 0; j < 4; j++)
#pragma unroll
            for (int q = 0; q < 4; q++) cacc[i][j][q] = 0.f;

    uint4 ra[4], rb[4];

    auto load_chunk = [&](int cc) {
        const int kk0 = cc * KC;
        const int tap = kk0 >> 9;
        const int d0 = kk0 & 511;
        const uint32_t* ap = Abat + (size_t)(t0 + lr + tap) * D_ + d0 + lc;
        const uint32_t* bp = Bt + (size_t)(n0 + lr) * KKtot + kk0 + lc;
#pragma unroll
        for (int i = 0; i < 4; i++) ra[i] = *(const uint4*)(ap + 4 * i);
#pragma unroll
        for (int i = 0; i < 4; i++) rb[i] = *(const uint4*)(bp + 4 * i);
    };
    auto store_chunk = [&](int st) {
        char* s = stp_base + st * STAGEB;
#pragma unroll
        for (int i = 0; i < 4; i++) {
            uint4 p = ra[i];
            *(uint2*)(s + 8 * i) = make_uint2((p.x >> 16) | (p.y & 0xFFFF0000u),
                                              (p.z >> 16) | (p.w & 0xFFFF0000u));
            *(uint2*)(s + TILEB + 8 * i) = make_uint2((p.x << 16 >> 16) | (p.y << 16),
                                                      (p.z << 16 >> 16) | (p.w << 16));
        }
#pragma unroll
        for (int i = 0; i < 4; i++) {
            uint4 p = rb[i];
            *(uint2*)(s + 2 * TILEB + 8 * i) = make_uint2((p.x >> 16) | (p.y & 0xFFFF0000u),
                                                          (p.z >> 16) | (p.w & 0xFFFF0000u));
            *(uint2*)(s + 3 * TILEB + 8 * i) = make_uint2((p.x << 16 >> 16) | (p.y << 16),
                                                          (p.z << 16 >> 16) | (p.w << 16));
        }
    };
    auto compute = [&](int st) {
        const uint32_t AH = sbase + st * STAGEB;
#pragma unroll
        for (int k16 = 0; k16 < 2; k16++) {
            const uint32_t kof = k16 * 32;
            uint32_t ah[4][4], al[4][4], bh[4][2], bl[4][2];
#pragma unroll
            for (int mf = 0; mf < 4; mf++) {
                uint32_t ad = AH + a_off + mf * (16 * ROWB) + kof;
                LDM_X4(ah[mf][0], ah[mf][1], ah[mf][2], ah[mf][3], ad);
                LDM_X4(al[mf][0], al[mf][1], al[mf][2], al[mf][3], ad + TILEB);
            }
#pragma unroll
            for (int nfp = 0; nfp < 2; nfp++) {
                uint32_t bd = AH + 2 * TILEB + b_off + nfp * (16 * ROWB) + kof;
                LDM_X4(bh[2 * nfp][0], bh[2 * nfp][1], bh[2 * nfp + 1][0], bh[2 * nfp + 1][1], bd);
                LDM_X4(bl[2 * nfp][0], bl[2 * nfp][1], bl[2 * nfp + 1][0], bl[2 * nfp + 1][1], bd + TILEB);
            }
#pragma unroll
            for (int mf = 0; mf < 4; mf++)
#pragma unroll
                for (int nf = 0; nf < 4; nf++) {
                    mma_bf16(cacc[mf][nf], ah[mf], bh[nf]);
                    mma_bf16(cacc[mf][nf], al[mf], bh[nf]);
                    mma_bf16(cacc[mf][nf], ah[mf], bl[nf]);
                }
        }
    };

    load_chunk(0);
    store_chunk(0);
    __syncthreads();
    if (NCH > 1) load_chunk(1);

    for (int cc = 0; cc < NCH; cc++) {
        compute(cc & 1);
        __syncthreads();
        if (cc + 1 < NCH) {
            store_chunk((cc + 1) & 1);
            __syncthreads();
            if (cc + 2 < NCH) load_chunk(cc + 2);
        }
    }

    // ---------------- epilogue ----------------
    const int r0 = lane >> 2;
    const int cq = (lane & 3) * 2;
    float mul0[4], mul1[4], add0[4], add1[4];
#pragma unroll
    for (int nf = 0; nf < 4; nf++) {
        int n = n0 + wn * 32 + nf * 8 + cq;
        float b0 = __ldg(&bias[n]), b1 = __ldg(&bias[n + 1]);
        if (MODE == 0) {
            float s0 = __ldg(&bng[n]) * rsqrtf(__ldg(&bnv[n]) + 1e-3f);
            float s1 = __ldg(&bng[n + 1]) * rsqrtf(__ldg(&bnv[n + 1]) + 1e-3f);
            mul0[nf] = s0; mul1[nf] = s1;
            add0[nf] = s0 * (b0 - __ldg(&bnm[n])) + __ldg(&bnb[n]);
            add1[nf] = s1 * (b1 - __ldg(&bnm[n + 1])) + __ldg(&bnb[n + 1]);
        } else {
            mul0[nf] = 1.f; mul1[nf] = 1.f;
            add0[nf] = b0;  add1[nf] = b1;
        }
    }

#pragma unroll
    for (int mf = 0; mf < 4; mf++) {
#pragma unroll
        for (int half = 0; half < 2; half++) {
            int m = wm * 64 + mf * 16 + r0 + half * 8;
#pragma unroll
            for (int nf = 0; nf < 4; nf++) {
                float v0 = fmaf(cacc[mf][nf][2 * half + 0], mul0[nf], add0[nf]);
                float v1 = fmaf(cacc[mf][nf][2 * half + 1], mul1[nf], add1[nf]);
                int nc = n0 + wn * 32 + nf * 8 + cq;
                if (MODE == 0) {
                    v0 = fmaxf(v0, 0.f);
                    v1 = fmaxf(v1, 0.f);
                    uint32_t* Cp = (uint32_t*)Cout;
                    size_t off = (size_t)bz * XPD_ + (size_t)(t0 + m + 2) * D_ + nc;
                    *(uint2*)(Cp + off) = make_uint2(pack_hl(v0), pack_hl(v1));
                } else {
                    float* Cf = (float*)Cout;
                    int t = t0 + m;
                    size_t off = (MODE == 1)
                        ? ((size_t)t * B_ + bz) * G4_ + nc
                        : ((size_t)(T_ - 1 - t) * B_ + bz) * G4_ + nc;
                    *(float2*)(Cf + off) = make_float2(v0, v1);
                }
            }
        }
    }
}

// ---------------- persistent bi-LSTM recurrence (unchanged, known-good) ----------------
__global__ __launch_bounds__(256) void lstm_kernel(
    const float* __restrict__ pre_f, const float* __restrict__ pre_b,
    const float* __restrict__ wr_f,  const float* __restrict__ wr_b,
    float* __restrict__ out)
{
    extern __shared__ float sm[];
    float* sW = sm;            // [256][16]
    float* sH = sm + 4096;     // [64][260]

    const int bx  = blockIdx.x;
    const int dir = bx >> 6;
    const int u0  = (bx & 63) << 2;
    const float* pre = dir ? pre_b : pre_f;
    const float* Wr  = dir ? wr_b  : wr_f;
    unsigned* bar = &g_bar[dir];

    const int tid = threadIdx.x;
    const int b = tid >> 2, q = tid & 3, u = u0 + q;

    for (int idx = tid; idx < 4096; idx += 256) {
        int k = idx >> 4, rr = idx & 15, qq = rr >> 2, g = rr & 3;
        sW[idx] = Wr[(size_t)k * G4_ + g * U_ + u0 + qq];
    }

    float c = 0.f;
    float* h0 = &g_h[dir][0][0];
    float* h1 = &g_h[dir][1][0];
    __syncthreads();

    for (int t = 0; t < T_; t++) {
        const float* hr = ((t + 1) & 1) ? h1 : h0;
        for (int idx = tid * 4; idx < B_ * U_; idx += 1024) {
            float4 v = __ldcg((const float4*)(hr + idx));
            int row = idx >> 8, col = idx & 255;
            *(float4*)&sH[row * 260 + col] = v;
        }
        __syncthreads();

        const float* p = pre + ((size_t)t * B_ + b) * G4_ + u;
        float z0 = p[0], z1 = p[U_], z2 = p[2 * U_], z3 = p[3 * U_];
        const float* hrow = &sH[b * 260];
#pragma unroll 8
        for (int k = 0; k < U_; k++) {
            float hv = hrow[k];
            float4 w = *(const float4*)&sW[k * 16 + q * 4];
            z0 += hv * w.x;
            z1 += hv * w.y;
            z2 += hv * w.z;
            z3 += hv * w.w;
        }
        float ig = 1.f / (1.f + __expf(-z0));
        float fg = 1.f / (1.f + __expf(-z1));
        float gg = tanhf(z2);
        float og = 1.f / (1.f + __expf(-z3));
        c = fg * c + ig * gg;
        float h = og * tanhf(c);

        float* hw = (t & 1) ? h1 : h0;
        hw[b * U_ + u] = h;
        int tout = dir ? (T_ - 1 - t) : t;
        out[((size_t)b * T_ + tout) * (2 * U_) + dir * U_ + u] = h;

        __syncthreads();
        if (tid == 0) {
            __threadfence();
            atomicAdd(bar, 1u);
            unsigned target = (unsigned)(t + 1) * RNN_CTAS;
            unsigned v;
            do {
                asm volatile("ld.global.acquire.gpu.u32 %0, [%1];" : "=r"(v) : "l"(bar));
            } while (v < target);
        }
        __syncthreads();
    }
}

// ---------------- launcher ----------------
extern "C" void kernel_launch(void* const* d_in, const int* in_sizes, int n_in,
                              void* d_out, int out_size)
{
    const float* inputs = (const float*)d_in[0];
    const float* convk  = (const float*)d_in[1];
    const float* convb  = (const float*)d_in[2];
    const float* bng    = (const float*)d_in[3];
    const float* bnb    = (const float*)d_in[4];
    const float* bnm    = (const float*)d_in[5];
    const float* bnv    = (const float*)d_in[6];
    const float* wk_f   = (const float*)d_in[7];
    const float* wr_f   = (const float*)d_in[8];
    const float* bi_f   = (const float*)d_in[9];
    const float* wk_b   = (const float*)d_in[10];
    const float* wr_b   = (const float*)d_in[11];
    const float* bi_b   = (const float*)d_in[12];
    float* out = (float*)d_out;

    uint32_t *xp0, *xp1, *wtc, *wtl;
    float *pre_f, *pre_b;
    cudaGetSymbolAddress((void**)&xp0,   g_xp0p);
    cudaGetSymbolAddress((void**)&xp1,   g_xp1p);
    cudaGetSymbolAddress((void**)&wtc,   g_wtc);
    cudaGetSymbolAddress((void**)&wtl,   g_wtl);
    cudaGetSymbolAddress((void**)&pre_f, g_pre_f);
    cudaGetSymbolAddress((void**)&pre_b, g_pre_b);

    cudaFuncSetAttribute(mma_gemm<0>, cudaFuncAttributeMaxDynamicSharedMemorySize, GSMEM);
    cudaFuncSetAttribute(mma_gemm<1>, cudaFuncAttributeMaxDynamicSharedMemorySize, GSMEM);
    cudaFuncSetAttribute(mma_gemm<2>, cudaFuncAttributeMaxDynamicSharedMemorySize, GSMEM);

    init_kernel<<<512, 256>>>();
    pad_pack<<<8192, 256>>>(inputs);
    wprep<<<8192, 256>>>(convk, wk_f, wk_b);

    const size_t wcs = (size_t)512 * 2560;
    dim3 gc(D_ / BN, T_ / BM, B_);           // (4, 8, 64)
    mma_gemm<0><<<gc, 256, GSMEM>>>(xp0, wtc + 0 * wcs, KTAP * D_,
                                    convb + 0 * D_, bng + 0 * D_, bnb + 0 * D_,
                                    bnm + 0 * D_, bnv + 0 * D_, xp1);
    mma_gemm<0><<<gc, 256, GSMEM>>>(xp1, wtc + 1 * wcs, KTAP * D_,
                                    convb + 1 * D_, bng + 1 * D_, bnb + 1 * D_,
                                    bnm + 1 * D_, bnv + 1 * D_, xp0);
    mma_gemm<0><<<gc, 256, GSMEM>>>(xp0, wtc + 2 * wcs, KTAP * D_,
                                    convb + 2 * D_, bng + 2 * D_, bnb + 2 * D_,
                                    bnm + 2 * D_, bnv + 2 * D_, xp1);

    const size_t wls = (size_t)1024 * 512;
    dim3 gl(G4_ / BN, T_ / BM, B_);          // (8, 8, 64)
    mma_gemm<1><<<gl, 256, GSMEM>>>(xp1 + 2 * D_, wtl + 0 * wls, D_,
                                    bi_f, bng, bnb, bnm, bnv, pre_f);
    mma_gemm<2><<<gl, 256, GSMEM>>>(xp1 + 2 * D_, wtl + 1 * wls, D_,
                                    bi_b, bng, bnb, bnm, bnv, pre_b);

    const int lstm_smem = (4096 + 64 * 260) * (int)sizeof(float);
    cudaFuncSetAttribute(lstm_kernel, cudaFuncAttributeMaxDynamicSharedMemorySize, lstm_smem);
    lstm_kernel<<<2 * RNN_CTAS, 256, lstm_smem>>>(pre_f, pre_b, wr_f, wr_b, out);
}

// round 4
// speedup vs baseline: 1.4509x; 1.0180x over previous
#include <cuda_runtime.h>
#include <cuda_bf16.h>
#include <cstdint>
#include <math.h>

#define B_    64
#define T_    1024
#define D_    512
#define KTAP  5
#define U_    256
#define G4_   1024
#define TP_   (T_ + 4)
#define XPD_  (TP_ * D_)
#define RNN_CTAS 64

#define BM    128
#define BN    128
#define KC    32                 // bf16 k per chunk
#define ROWB  80                 // smem row stride (bytes) -> conflict-free ldmatrix
#define TILEB (128 * ROWB)       // 10240 B per tile
#define STAGEB (4 * TILEB)       // AH, AL, BH, BL
#define NSTG  3
#define GSMEM (NSTG * STAGEB)

// ---------------- scratch: separate hi/lo bf16 planes ----------------
__device__ uint16_t g_xh0[(size_t)B_ * XPD_];
__device__ uint16_t g_xl0[(size_t)B_ * XPD_];
__device__ uint16_t g_xh1[(size_t)B_ * XPD_];
__device__ uint16_t g_xl1[(size_t)B_ * XPD_];
__device__ uint16_t g_wch[(size_t)3 * 512 * 2560];  // conv weights [i][n][kk]
__device__ uint16_t g_wcl[(size_t)3 * 512 * 2560];
__device__ uint16_t g_wlh[(size_t)2 * 1024 * 512];  // lstm kernels [dir][n][d]
__device__ uint16_t g_wll[(size_t)2 * 1024 * 512];
__device__ float    g_pre_f[(size_t)T_ * B_ * G4_];
__device__ float    g_pre_b[(size_t)T_ * B_ * G4_];
__device__ float    g_h[2][2][B_ * U_];
__device__ unsigned g_bar[2];

// ---------------- helpers ----------------
__device__ __forceinline__ uint32_t smem_u32(const void* p) {
    uint32_t a;
    asm("{ .reg .u64 t; cvta.to.shared.u64 t, %1; cvt.u32.u64 %0, t; }" : "=r"(a) : "l"(p));
    return a;
}
__device__ __forceinline__ void split_hl(float v, uint16_t& h, uint16_t& l) {
    __nv_bfloat16 bh = __float2bfloat16(v);
    float hf = __bfloat162float(bh);
    __nv_bfloat16 bl = __float2bfloat16(v - hf);
    h = __bfloat16_as_ushort(bh);
    l = __bfloat16_as_ushort(bl);
}
#define CP16(dst, src) \
    asm volatile("cp.async.cg.shared.global [%0], [%1], 16;" :: "r"(dst), "l"(src))
#define CP_COMMIT() asm volatile("cp.async.commit_group;" ::: "memory")
#define CP_WAIT(N)  asm volatile("cp.async.wait_group %0;" :: "n"(N) : "memory")
#define LDM_X4(R0, R1, R2, R3, ADDR)                                            \
    asm volatile("ldmatrix.sync.aligned.m8n8.x4.shared.b16 {%0,%1,%2,%3}, [%4];"\
        : "=r"(R0), "=r"(R1), "=r"(R2), "=r"(R3) : "r"(ADDR))
__device__ __forceinline__ void mma_bf16(float* c, const uint32_t* a, const uint32_t* b) {
    asm volatile(
        "mma.sync.aligned.m16n8k16.row.col.f32.bf16.bf16.f32 "
        "{%0,%1,%2,%3}, {%4,%5,%6,%7}, {%8,%9}, {%0,%1,%2,%3};"
        : "+f"(c[0]), "+f"(c[1]), "+f"(c[2]), "+f"(c[3])
        : "r"(a[0]), "r"(a[1]), "r"(a[2]), "r"(a[3]), "r"(b[0]), "r"(b[1]));
}

// ---------------- init ----------------
__global__ void init_kernel() {
    int idx = blockIdx.x * blockDim.x + threadIdx.x;
    int nh = B_ * 4 * D_;
    if (idx < nh) {
        int b = idx / (4 * D_);
        int r = (idx / D_) & 3;
        int d = idx % D_;
        int row = (r < 2) ? r : (TP_ - 4 + r);
        size_t o = (size_t)b * XPD_ + (size_t)row * D_ + d;
        g_xh0[o] = 0; g_xl0[o] = 0; g_xh1[o] = 0; g_xl1[o] = 0;
    }
    if (idx < 2 * 2 * B_ * U_) ((float*)g_h)[idx] = 0.f;
    if (idx < 2) g_bar[idx] = 0u;
}

// ---------------- pack input ----------------
__global__ void pad_pack(const float* __restrict__ in) {
    size_t total = (size_t)B_ * T_ * D_;
    for (size_t idx = (size_t)blockIdx.x * blockDim.x + threadIdx.x;
         idx < total; idx += (size_t)gridDim.x * blockDim.x) {
        size_t b = idx / ((size_t)T_ * D_);
        size_t r = idx % ((size_t)T_ * D_);
        size_t t = r / D_, d = r % D_;
        size_t o = b * XPD_ + (t + 2) * D_ + d;
        uint16_t h, l;
        split_hl(in[idx], h, l);
        g_xh0[o] = h; g_xl0[o] = l;
    }
}

// ---------------- transpose + split weights ----------------
__global__ void wprep(const float* __restrict__ convk,
                      const float* __restrict__ wkf, const float* __restrict__ wkb) {
    const size_t CONVN = (size_t)3 * 512 * 2560;
    const size_t LSTMN = (size_t)1024 * 512;
    size_t total = CONVN + 2 * LSTMN;
    for (size_t idx = (size_t)blockIdx.x * blockDim.x + threadIdx.x;
         idx < total; idx += (size_t)gridDim.x * blockDim.x) {
        uint16_t h, l;
        if (idx < CONVN) {
            size_t i = idx / ((size_t)512 * 2560);
            size_t r = idx % ((size_t)512 * 2560);
            size_t n = r / 2560, kk = r % 2560;
            size_t tap = kk >> 9, din = kk & 511;
            split_hl(convk[(((i * KTAP + tap) * D_) + din) * D_ + n], h, l);
            g_wch[idx] = h; g_wcl[idx] = l;
        } else if (idx < CONVN + LSTMN) {
            size_t j = idx - CONVN;
            size_t n = j >> 9, d = j & 511;
            split_hl(wkf[d * G4_ + n], h, l);
            g_wlh[j] = h; g_wll[j] = l;
        } else {
            size_t j = idx - CONVN - LSTMN;
            size_t n = j >> 9, d = j & 511;
            split_hl(wkb[d * G4_ + n], h, l);
            g_wlh[LSTMN + j] = h; g_wll[LSTMN + j] = l;
        }
    }
}

// ---------------- cp.async pipelined warp-MMA split-bf16 GEMM ----------------
// MODE 0: conv (bias, BN, ReLU) -> hi/lo plane interior
// MODE 1/2: lstm pre (+bias) -> fp32 [(t or T-1-t)*B + b][G4]
template <int MODE>
__global__ __launch_bounds__(256, 1) void mma_gemm(
    const uint16_t* __restrict__ Ah, const uint16_t* __restrict__ Al,
    const uint16_t* __restrict__ Bh, const uint16_t* __restrict__ Bl,
    int KKtot,
    const float* __restrict__ bias,
    const float* __restrict__ bng, const float* __restrict__ bnb,
    const float* __restrict__ bnm, const float* __restrict__ bnv,
    uint16_t* __restrict__ Ch, uint16_t* __restrict__ Cl,
    float* __restrict__ Cf)
{
    extern __shared__ char smraw[];
    const uint32_t sbase = smem_u32(smraw);

    const int tid = threadIdx.x;
    const int wid = tid >> 5, lane = tid & 31;
    const int bz = blockIdx.z;
    const int t0 = blockIdx.y * BM;
    const int n0 = blockIdx.x * BN;
    const int wm = wid & 1;      // row group: wm*64
    const int wn = wid >> 1;     // col group: wn*32

    // ldmatrix per-lane offsets (same as R3)
    const uint32_t a_off = (uint32_t)((wm * 64 + (lane & 15)) * ROWB + (lane >> 4) * 16);
    const uint32_t b_off = (uint32_t)((wn * 32 + (lane & 7) + ((lane >> 4) << 3)) * ROWB
                                      + ((lane >> 3) & 1) * 16);

    const uint16_t* Ahb = Ah + (size_t)bz * XPD_;
    const uint16_t* Alb = Al + (size_t)bz * XPD_;
    const int NCH = KKtot / KC;

    float cacc[4][4][4];
#pragma unroll
    for (int i = 0; i < 4; i++)
#pragma unroll
        for (int j = 0; j < 4; j++)
#pragma unroll
            for (int q = 0; q < 4; q++) cacc[i][j][q] = 0.f;

    // loader: each thread copies 2 segments per tile (512 segs/tile), 8 cp.async total
    auto issue = [&](int cc) {
        const int st = cc % NSTG;
        const int kk0 = cc * KC;
        const int tap = kk0 >> 9;
        const int d0 = kk0 & 511;
        const uint32_t sb = sbase + st * STAGEB;
#pragma unroll
        for (int half = 0; half < 2; half++) {
            const int s = tid + half * 256;
            const int row = s >> 2, seg = s & 3;
            const uint32_t doff = (uint32_t)(row * ROWB + seg * 16);
            const size_t aoff = (size_t)(t0 + row + tap) * D_ + d0 + seg * 8;
            const size_t boff = (size_t)(n0 + row) * KKtot + kk0 + seg * 8;
            CP16(sb + doff,             Ahb + aoff);
            CP16(sb + TILEB + doff,     Alb + aoff);
            CP16(sb + 2 * TILEB + doff, Bh + boff);
            CP16(sb + 3 * TILEB + doff, Bl + boff);
        }
        CP_COMMIT();
    };

    auto compute = [&](int st) {
        const uint32_t SB = sbase + st * STAGEB;
#pragma unroll
        for (int k16 = 0; k16 < 2; k16++) {
            const uint32_t kof = k16 * 32;
            uint32_t ah[4][4], al[4][4], bh[4][2], bl[4][2];
#pragma unroll
            for (int mf = 0; mf < 4; mf++) {
                uint32_t ad = SB + a_off + mf * (16 * ROWB) + kof;
                LDM_X4(ah[mf][0], ah[mf][1], ah[mf][2], ah[mf][3], ad);
                LDM_X4(al[mf][0], al[mf][1], al[mf][2], al[mf][3], ad + TILEB);
            }
#pragma unroll
            for (int nfp = 0; nfp < 2; nfp++) {
                uint32_t bd = SB + 2 * TILEB + b_off + nfp * (16 * ROWB) + kof;
                LDM_X4(bh[2 * nfp][0], bh[2 * nfp][1], bh[2 * nfp + 1][0], bh[2 * nfp + 1][1], bd);
                LDM_X4(bl[2 * nfp][0], bl[2 * nfp][1], bl[2 * nfp + 1][0], bl[2 * nfp + 1][1], bd + TILEB);
            }
#pragma unroll
            for (int mf = 0; mf < 4; mf++)
#pragma unroll
                for (int nf = 0; nf < 4; nf++) {
                    mma_bf16(cacc[mf][nf], ah[mf], bh[nf]);
                    mma_bf16(cacc[mf][nf], al[mf], bh[nf]);
                    mma_bf16(cacc[mf][nf], ah[mf], bl[nf]);
                }
        }
    };

    // prologue: 2 chunks in flight
    issue(0);
    if (NCH > 1) issue(1);

    for (int cc = 0; cc < NCH; cc++) {
        CP_WAIT(1);
        __syncthreads();
        compute(cc % NSTG);
        __syncthreads();
        const int nc = cc + NSTG - 1;
        if (nc < NCH) issue(nc);
    }

    // ---------------- epilogue ----------------
    const int r0 = lane >> 2;
    const int cq = (lane & 3) * 2;
    float mul0[4], mul1[4], add0[4], add1[4];
#pragma unroll
    for (int nf = 0; nf < 4; nf++) {
        int n = n0 + wn * 32 + nf * 8 + cq;
        float b0 = __ldg(&bias[n]), b1 = __ldg(&bias[n + 1]);
        if (MODE == 0) {
            float s0 = __ldg(&bng[n]) * rsqrtf(__ldg(&bnv[n]) + 1e-3f);
            float s1 = __ldg(&bng[n + 1]) * rsqrtf(__ldg(&bnv[n + 1]) + 1e-3f);
            mul0[nf] = s0; mul1[nf] = s1;
            add0[nf] = s0 * (b0 - __ldg(&bnm[n])) + __ldg(&bnb[n]);
            add1[nf] = s1 * (b1 - __ldg(&bnm[n + 1])) + __ldg(&bnb[n + 1]);
        } else {
            mul0[nf] = 1.f; mul1[nf] = 1.f;
            add0[nf] = b0;  add1[nf] = b1;
        }
    }

#pragma unroll
    for (int mf = 0; mf < 4; mf++) {
#pragma unroll
        for (int half = 0; half < 2; half++) {
            int m = wm * 64 + mf * 16 + r0 + half * 8;
#pragma unroll
            for (int nf = 0; nf < 4; nf++) {
                float v0 = fmaf(cacc[mf][nf][2 * half + 0], mul0[nf], add0[nf]);
                float v1 = fmaf(cacc[mf][nf][2 * half + 1], mul1[nf], add1[nf]);
                int nc = n0 + wn * 32 + nf * 8 + cq;
                if (MODE == 0) {
                    v0 = fmaxf(v0, 0.f);
                    v1 = fmaxf(v1, 0.f);
                    uint16_t h0, l0, h1, l1;
                    split_hl(v0, h0, l0);
                    split_hl(v1, h1, l1);
                    size_t off = (size_t)bz * XPD_ + (size_t)(t0 + m + 2) * D_ + nc;
                    *(uint32_t*)(Ch + off) = (uint32_t)h0 | ((uint32_t)h1 << 16);
                    *(uint32_t*)(Cl + off) = (uint32_t)l0 | ((uint32_t)l1 << 16);
                } else {
                    int t = t0 + m;
                    size_t off = (MODE == 1)
                        ? ((size_t)t * B_ + bz) * G4_ + nc
                        : ((size_t)(T_ - 1 - t) * B_ + bz) * G4_ + nc;
                    *(float2*)(Cf + off) = make_float2(v0, v1);
                }
            }
        }
    }
}

// ---------------- persistent bi-LSTM recurrence (unchanged, known-good) ----------------
__global__ __launch_bounds__(256) void lstm_kernel(
    const float* __restrict__ pre_f, const float* __restrict__ pre_b,
    const float* __restrict__ wr_f,  const float* __restrict__ wr_b,
    float* __restrict__ out)
{
    extern __shared__ float sm[];
    float* sW = sm;            // [256][16]
    float* sH = sm + 4096;     // [64][260]

    const int bx  = blockIdx.x;
    const int dir = bx >> 6;
    const int u0  = (bx & 63) << 2;
    const float* pre = dir ? pre_b : pre_f;
    const float* Wr  = dir ? wr_b  : wr_f;
    unsigned* bar = &g_bar[dir];

    const int tid = threadIdx.x;
    const int b = tid >> 2, q = tid & 3, u = u0 + q;

    for (int idx = tid; idx < 4096; idx += 256) {
        int k = idx >> 4, rr = idx & 15, qq = rr >> 2, g = rr & 3;
        sW[idx] = Wr[(size_t)k * G4_ + g * U_ + u0 + qq];
    }

    float c = 0.f;
    float* h0 = &g_h[dir][0][0];
    float* h1 = &g_h[dir][1][0];
    __syncthreads();

    for (int t = 0; t < T_; t++) {
        const float* hr = ((t + 1) & 1) ? h1 : h0;
        for (int idx = tid * 4; idx < B_ * U_; idx += 1024) {
            float4 v = __ldcg((const float4*)(hr + idx));
            int row = idx >> 8, col = idx & 255;
            *(float4*)&sH[row * 260 + col] = v;
        }
        __syncthreads();

        const float* p = pre + ((size_t)t * B_ + b) * G4_ + u;
        float z0 = p[0], z1 = p[U_], z2 = p[2 * U_], z3 = p[3 * U_];
        const float* hrow = &sH[b * 260];
#pragma unroll 8
        for (int k = 0; k < U_; k++) {
            float hv = hrow[k];
            float4 w = *(const float4*)&sW[k * 16 + q * 4];
            z0 += hv * w.x;
            z1 += hv * w.y;
            z2 += hv * w.z;
            z3 += hv * w.w;
        }
        float ig = 1.f / (1.f + __expf(-z0));
        float fg = 1.f / (1.f + __expf(-z1));
        float gg = tanhf(z2);
        float og = 1.f / (1.f + __expf(-z3));
        c = fg * c + ig * gg;
        float h = og * tanhf(c);

        float* hw = (t & 1) ? h1 : h0;
        hw[b * U_ + u] = h;
        int tout = dir ? (T_ - 1 - t) : t;
        out[((size_t)b * T_ + tout) * (2 * U_) + dir * U_ + u] = h;

        __syncthreads();
        if (tid == 0) {
            __threadfence();
            atomicAdd(bar, 1u);
            unsigned target = (unsigned)(t + 1) * RNN_CTAS;
            unsigned v;
            do {
                asm volatile("ld.global.acquire.gpu.u32 %0, [%1];" : "=r"(v) : "l"(bar));
            } while (v < target);
        }
        __syncthreads();
    }
}

// ---------------- launcher ----------------
extern "C" void kernel_launch(void* const* d_in, const int* in_sizes, int n_in,
                              void* d_out, int out_size)
{
    const float* inputs = (const float*)d_in[0];
    const float* convk  = (const float*)d_in[1];
    const float* convb  = (const float*)d_in[2];
    const float* bng    = (const float*)d_in[3];
    const float* bnb    = (const float*)d_in[4];
    const float* bnm    = (const float*)d_in[5];
    const float* bnv    = (const float*)d_in[6];
    const float* wk_f   = (const float*)d_in[7];
    const float* wr_f   = (const float*)d_in[8];
    const float* bi_f   = (const float*)d_in[9];
    const float* wk_b   = (const float*)d_in[10];
    const float* wr_b   = (const float*)d_in[11];
    const float* bi_b   = (const float*)d_in[12];
    float* out = (float*)d_out;

    uint16_t *xh0, *xl0, *xh1, *xl1, *wch, *wcl, *wlh, *wll;
    float *pre_f, *pre_b;
    cudaGetSymbolAddress((void**)&xh0, g_xh0);
    cudaGetSymbolAddress((void**)&xl0, g_xl0);
    cudaGetSymbolAddress((void**)&xh1, g_xh1);
    cudaGetSymbolAddress((void**)&xl1, g_xl1);
    cudaGetSymbolAddress((void**)&wch, g_wch);
    cudaGetSymbolAddress((void**)&wcl, g_wcl);
    cudaGetSymbolAddress((void**)&wlh, g_wlh);
    cudaGetSymbolAddress((void**)&wll, g_wll);
    cudaGetSymbolAddress((void**)&pre_f, g_pre_f);
    cudaGetSymbolAddress((void**)&pre_b, g_pre_b);

    cudaFuncSetAttribute(mma_gemm<0>, cudaFuncAttributeMaxDynamicSharedMemorySize, GSMEM);
    cudaFuncSetAttribute(mma_gemm<1>, cudaFuncAttributeMaxDynamicSharedMemorySize, GSMEM);
    cudaFuncSetAttribute(mma_gemm<2>, cudaFuncAttributeMaxDynamicSharedMemorySize, GSMEM);

    init_kernel<<<512, 256>>>();
    pad_pack<<<8192, 256>>>(inputs);
    wprep<<<8192, 256>>>(convk, wk_f, wk_b);

    const size_t wcs = (size_t)512 * 2560;
    dim3 gc(D_ / BN, T_ / BM, B_);           // (4, 8, 64)
    mma_gemm<0><<<gc, 256, GSMEM>>>(xh0, xl0, wch + 0 * wcs, wcl + 0 * wcs, KTAP * D_,
                                    convb + 0 * D_, bng + 0 * D_, bnb + 0 * D_,
                                    bnm + 0 * D_, bnv + 0 * D_, xh1, xl1, nullptr);
    mma_gemm<0><<<gc, 256, GSMEM>>>(xh1, xl1, wch + 1 * wcs, wcl + 1 * wcs, KTAP * D_,
                                    convb + 1 * D_, bng + 1 * D_, bnb + 1 * D_,
                                    bnm + 1 * D_, bnv + 1 * D_, xh0, xl0, nullptr);
    mma_gemm<0><<<gc, 256, GSMEM>>>(xh0, xl0, wch + 2 * wcs, wcl + 2 * wcs, KTAP * D_,
                                    convb + 2 * D_, bng + 2 * D_, bnb + 2 * D_,
                                    bnm + 2 * D_, bnv + 2 * D_, xh1, xl1, nullptr);

    const size_t wls = (size_t)1024 * 512;
    dim3 gl(G4_ / BN, T_ / BM, B_);          // (8, 8, 64)
    mma_gemm<1><<<gl, 256, GSMEM>>>(xh1 + 2 * D_, xl1 + 2 * D_, wlh + 0 * wls, wll + 0 * wls, D_,
                                    bi_f, bng, bnb, bnm, bnv, nullptr, nullptr, pre_f);
    mma_gemm<2><<<gl, 256, GSMEM>>>(xh1 + 2 * D_, xl1 + 2 * D_, wlh + 1 * wls, wll + 1 * wls, D_,
                                    bi_b, bng, bnb, bnm, bnv, nullptr, nullptr, pre_b);

    const int lstm_smem = (4096 + 64 * 260) * (int)sizeof(float);
    cudaFuncSetAttribute(lstm_kernel, cudaFuncAttributeMaxDynamicSharedMemorySize, lstm_smem);
    lstm_kernel<<<2 * RNN_CTAS, 256, lstm_smem>>>(pre_f, pre_b, wr_f, wr_b, out);
}

// round 5
// speedup vs baseline: 1.5746x; 1.0852x over previous
#include <cuda_runtime.h>
#include <cuda_bf16.h>
#include <cstdint>
#include <math.h>

#define B_    64
#define T_    1024
#define D_    512
#define KTAP  5
#define U_    256
#define G4_   1024
#define TP_   (T_ + 4)
#define XPD_  (TP_ * D_)
#define RNN_CTAS 64

#define BM    128
#define BN    128
#define KC    32                 // bf16 k per chunk
#define ROWB  80                 // smem row stride (bytes) -> conflict-free ldmatrix
#define TILEB (128 * ROWB)       // 10240 B per tile
#define STAGEB (4 * TILEB)       // AH, AL, BH, BL
#define NSTG  2
#define GSMEM (NSTG * STAGEB)    // 80 KB -> 2 CTAs/SM

// ---------------- scratch: separate hi/lo bf16 planes ----------------
__device__ uint16_t g_xh0[(size_t)B_ * XPD_];
__device__ uint16_t g_xl0[(size_t)B_ * XPD_];
__device__ uint16_t g_xh1[(size_t)B_ * XPD_];
__device__ uint16_t g_xl1[(size_t)B_ * XPD_];
__device__ uint16_t g_wch[(size_t)3 * 512 * 2560];  // conv weights [i][n][kk]
__device__ uint16_t g_wcl[(size_t)3 * 512 * 2560];
__device__ uint16_t g_wlh[(size_t)2 * 1024 * 512];  // lstm kernels [dir][n][d]
__device__ uint16_t g_wll[(size_t)2 * 1024 * 512];
__device__ float    g_pre_f[(size_t)T_ * B_ * G4_];
__device__ float    g_pre_b[(size_t)T_ * B_ * G4_];
__device__ float    g_h[2][2][B_ * U_];
__device__ unsigned g_bar[2];

// ---------------- helpers ----------------
__device__ __forceinline__ uint32_t smem_u32(const void* p) {
    uint32_t a;
    asm("{ .reg .u64 t; cvta.to.shared.u64 t, %1; cvt.u32.u64 %0, t; }" : "=r"(a) : "l"(p));
    return a;
}
__device__ __forceinline__ void split_hl(float v, uint16_t& h, uint16_t& l) {
    __nv_bfloat16 bh = __float2bfloat16(v);
    float hf = __bfloat162float(bh);
    __nv_bfloat16 bl = __float2bfloat16(v - hf);
    h = __bfloat16_as_ushort(bh);
    l = __bfloat16_as_ushort(bl);
}
#define CP16(dst, src) \
    asm volatile("cp.async.cg.shared.global [%0], [%1], 16;" :: "r"(dst), "l"(src))
#define CP_COMMIT() asm volatile("cp.async.commit_group;" ::: "memory")
#define CP_WAIT(N)  asm volatile("cp.async.wait_group %0;" :: "n"(N) : "memory")
#define LDM_X4(R0, R1, R2, R3, ADDR)                                            \
    asm volatile("ldmatrix.sync.aligned.m8n8.x4.shared.b16 {%0,%1,%2,%3}, [%4];"\
        : "=r"(R0), "=r"(R1), "=r"(R2), "=r"(R3) : "r"(ADDR))
__device__ __forceinline__ void mma_bf16(float* c, const uint32_t* a, const uint32_t* b) {
    asm volatile(
        "mma.sync.aligned.m16n8k16.row.col.f32.bf16.bf16.f32 "
        "{%0,%1,%2,%3}, {%4,%5,%6,%7}, {%8,%9}, {%0,%1,%2,%3};"
        : "+f"(c[0]), "+f"(c[1]), "+f"(c[2]), "+f"(c[3])
        : "r"(a[0]), "r"(a[1]), "r"(a[2]), "r"(a[3]), "r"(b[0]), "r"(b[1]));
}

// ---------------- init ----------------
__global__ void init_kernel() {
    int idx = blockIdx.x * blockDim.x + threadIdx.x;
    int nh = B_ * 4 * D_;
    if (idx < nh) {
        int b = idx / (4 * D_);
        int r = (idx / D_) & 3;
        int d = idx % D_;
        int row = (r < 2) ? r : (TP_ - 4 + r);
        size_t o = (size_t)b * XPD_ + (size_t)row * D_ + d;
        g_xh0[o] = 0; g_xl0[o] = 0; g_xh1[o] = 0; g_xl1[o] = 0;
    }
    if (idx < 2 * 2 * B_ * U_) ((float*)g_h)[idx] = 0.f;
    if (idx < 2) g_bar[idx] = 0u;
}

// ---------------- pack input ----------------
__global__ void pad_pack(const float* __restrict__ in) {
    size_t total = (size_t)B_ * T_ * D_;
    for (size_t idx = (size_t)blockIdx.x * blockDim.x + threadIdx.x;
         idx < total; idx += (size_t)gridDim.x * blockDim.x) {
        size_t b = idx / ((size_t)T_ * D_);
        size_t r = idx % ((size_t)T_ * D_);
        size_t t = r / D_, d = r % D_;
        size_t o = b * XPD_ + (t + 2) * D_ + d;
        uint16_t h, l;
        split_hl(in[idx], h, l);
        g_xh0[o] = h; g_xl0[o] = l;
    }
}

// ---------------- transpose + split weights ----------------
__global__ void wprep(const float* __restrict__ convk,
                      const float* __restrict__ wkf, const float* __restrict__ wkb) {
    const size_t CONVN = (size_t)3 * 512 * 2560;
    const size_t LSTMN = (size_t)1024 * 512;
    size_t total = CONVN + 2 * LSTMN;
    for (size_t idx = (size_t)blockIdx.x * blockDim.x + threadIdx.x;
         idx < total; idx += (size_t)gridDim.x * blockDim.x) {
        uint16_t h, l;
        if (idx < CONVN) {
            size_t i = idx / ((size_t)512 * 2560);
            size_t r = idx % ((size_t)512 * 2560);
            size_t n = r / 2560, kk = r % 2560;
            size_t tap = kk >> 9, din = kk & 511;
            split_hl(convk[(((i * KTAP + tap) * D_) + din) * D_ + n], h, l);
            g_wch[idx] = h; g_wcl[idx] = l;
        } else if (idx < CONVN + LSTMN) {
            size_t j = idx - CONVN;
            size_t n = j >> 9, d = j & 511;
            split_hl(wkf[d * G4_ + n], h, l);
            g_wlh[j] = h; g_wll[j] = l;
        } else {
            size_t j = idx - CONVN - LSTMN;
            size_t n = j >> 9, d = j & 511;
            split_hl(wkb[d * G4_ + n], h, l);
            g_wlh[LSTMN + j] = h; g_wll[LSTMN + j] = l;
        }
    }
}

// ---------------- cp.async pipelined warp-MMA split-bf16 GEMM, 2 CTAs/SM ----------------
// MODE 0: conv (bias, BN, ReLU) -> hi/lo plane interior
// MODE 1/2: lstm pre (+bias) -> fp32 [(t or T-1-t)*B + b][G4]
template <int MODE>
__global__ __launch_bounds__(256, 2) void mma_gemm(
    const uint16_t* __restrict__ Ah, const uint16_t* __restrict__ Al,
    const uint16_t* __restrict__ Bh, const uint16_t* __restrict__ Bl,
    int KKtot,
    const float* __restrict__ bias,
    const float* __restrict__ bng, const float* __restrict__ bnb,
    const float* __restrict__ bnm, const float* __restrict__ bnv,
    uint16_t* __restrict__ Ch, uint16_t* __restrict__ Cl,
    float* __restrict__ Cf)
{
    extern __shared__ char smraw[];
    const uint32_t sbase = smem_u32(smraw);

    const int tid = threadIdx.x;
    const int wid = tid >> 5, lane = tid & 31;
    const int bz = blockIdx.z;
    const int t0 = blockIdx.y * BM;
    const int n0 = blockIdx.x * BN;
    const int wm = wid & 1;      // row group: wm*64
    const int wn = wid >> 1;     // col group: wn*32

    const uint32_t a_off = (uint32_t)((wm * 64 + (lane & 15)) * ROWB + (lane >> 4) * 16);
    const uint32_t b_off = (uint32_t)((wn * 32 + (lane & 7) + ((lane >> 4) << 3)) * ROWB
                                      + ((lane >> 3) & 1) * 16);

    const uint16_t* Ahb = Ah + (size_t)bz * XPD_;
    const uint16_t* Alb = Al + (size_t)bz * XPD_;
    const int NCH = KKtot / KC;

    float cacc[4][4][4];
#pragma unroll
    for (int i = 0; i < 4; i++)
#pragma unroll
        for (int j = 0; j < 4; j++)
#pragma unroll
            for (int q = 0; q < 4; q++) cacc[i][j][q] = 0.f;

    auto issue = [&](int cc) {
        const int st = cc & 1;
        const int kk0 = cc * KC;
        const int tap = kk0 >> 9;
        const int d0 = kk0 & 511;
        const uint32_t sb = sbase + st * STAGEB;
#pragma unroll
        for (int half = 0; half < 2; half++) {
            const int s = tid + half * 256;
            const int row = s >> 2, seg = s & 3;
            const uint32_t doff = (uint32_t)(row * ROWB + seg * 16);
            const size_t aoff = (size_t)(t0 + row + tap) * D_ + d0 + seg * 8;
            const size_t boff = (size_t)(n0 + row) * KKtot + kk0 + seg * 8;
            CP16(sb + doff,             Ahb + aoff);
            CP16(sb + TILEB + doff,     Alb + aoff);
            CP16(sb + 2 * TILEB + doff, Bh + boff);
            CP16(sb + 3 * TILEB + doff, Bl + boff);
        }
        CP_COMMIT();
    };

    // compute with reduced fragment liveness: B frags resident, A frags streamed per-mf
    auto compute = [&](int st) {
        const uint32_t SB = sbase + st * STAGEB;
#pragma unroll
        for (int k16 = 0; k16 < 2; k16++) {
            const uint32_t kof = k16 * 32;
            uint32_t bh[4][2], bl[4][2];
#pragma unroll
            for (int nfp = 0; nfp < 2; nfp++) {
                uint32_t bd = SB + 2 * TILEB + b_off + nfp * (16 * ROWB) + kof;
                LDM_X4(bh[2 * nfp][0], bh[2 * nfp][1], bh[2 * nfp + 1][0], bh[2 * nfp + 1][1], bd);
                LDM_X4(bl[2 * nfp][0], bl[2 * nfp][1], bl[2 * nfp + 1][0], bl[2 * nfp + 1][1], bd + TILEB);
            }
#pragma unroll
            for (int mf = 0; mf < 4; mf++) {
                uint32_t ah[4], al[4];
                uint32_t ad = SB + a_off + mf * (16 * ROWB) + kof;
                LDM_X4(ah[0], ah[1], ah[2], ah[3], ad);
                LDM_X4(al[0], al[1], al[2], al[3], ad + TILEB);
#pragma unroll
                for (int nf = 0; nf < 4; nf++) {
                    mma_bf16(cacc[mf][nf], ah, bh[nf]);
                    mma_bf16(cacc[mf][nf], al, bh[nf]);
                    mma_bf16(cacc[mf][nf], ah, bl[nf]);
                }
            }
        }
    };

    // prologue: both buffers in flight
    issue(0);
    if (NCH > 1) issue(1);

    for (int cc = 0; cc < NCH; cc++) {
        CP_WAIT(1);
        __syncthreads();
        compute(cc & 1);
        __syncthreads();
        if (cc + 2 < NCH) issue(cc + 2);
    }

    // ---------------- epilogue ----------------
    const int r0 = lane >> 2;
    const int cq = (lane & 3) * 2;
    float mul0[4], mul1[4], add0[4], add1[4];
#pragma unroll
    for (int nf = 0; nf < 4; nf++) {
        int n = n0 + wn * 32 + nf * 8 + cq;
        float b0 = __ldg(&bias[n]), b1 = __ldg(&bias[n + 1]);
        if (MODE == 0) {
            float s0 = __ldg(&bng[n]) * rsqrtf(__ldg(&bnv[n]) + 1e-3f);
            float s1 = __ldg(&bng[n + 1]) * rsqrtf(__ldg(&bnv[n + 1]) + 1e-3f);
            mul0[nf] = s0; mul1[nf] = s1;
            add0[nf] = s0 * (b0 - __ldg(&bnm[n])) + __ldg(&bnb[n]);
            add1[nf] = s1 * (b1 - __ldg(&bnm[n + 1])) + __ldg(&bnb[n + 1]);
        } else {
            mul0[nf] = 1.f; mul1[nf] = 1.f;
            add0[nf] = b0;  add1[nf] = b1;
        }
    }

#pragma unroll
    for (int mf = 0; mf < 4; mf++) {
#pragma unroll
        for (int half = 0; half < 2; half++) {
            int m = wm * 64 + mf * 16 + r0 + half * 8;
#pragma unroll
            for (int nf = 0; nf < 4; nf++) {
                float v0 = fmaf(cacc[mf][nf][2 * half + 0], mul0[nf], add0[nf]);
                float v1 = fmaf(cacc[mf][nf][2 * half + 1], mul1[nf], add1[nf]);
                int nc = n0 + wn * 32 + nf * 8 + cq;
                if (MODE == 0) {
                    v0 = fmaxf(v0, 0.f);
                    v1 = fmaxf(v1, 0.f);
                    uint16_t h0, l0, h1, l1;
                    split_hl(v0, h0, l0);
                    split_hl(v1, h1, l1);
                    size_t off = (size_t)bz * XPD_ + (size_t)(t0 + m + 2) * D_ + nc;
                    *(uint32_t*)(Ch + off) = (uint32_t)h0 | ((uint32_t)h1 << 16);
                    *(uint32_t*)(Cl + off) = (uint32_t)l0 | ((uint32_t)l1 << 16);
                } else {
                    int t = t0 + m;
                    size_t off = (MODE == 1)
                        ? ((size_t)t * B_ + bz) * G4_ + nc
                        : ((size_t)(T_ - 1 - t) * B_ + bz) * G4_ + nc;
                    *(float2*)(Cf + off) = make_float2(v0, v1);
                }
            }
        }
    }
}

// ---------------- persistent bi-LSTM recurrence (unchanged, known-good) ----------------
__global__ __launch_bounds__(256) void lstm_kernel(
    const float* __restrict__ pre_f, const float* __restrict__ pre_b,
    const float* __restrict__ wr_f,  const float* __restrict__ wr_b,
    float* __restrict__ out)
{
    extern __shared__ float sm[];
    float* sW = sm;            // [256][16]
    float* sH = sm + 4096;     // [64][260]

    const int bx  = blockIdx.x;
    const int dir = bx >> 6;
    const int u0  = (bx & 63) << 2;
    const float* pre = dir ? pre_b : pre_f;
    const float* Wr  = dir ? wr_b  : wr_f;
    unsigned* bar = &g_bar[dir];

    const int tid = threadIdx.x;
    const int b = tid >> 2, q = tid & 3, u = u0 + q;

    for (int idx = tid; idx < 4096; idx += 256) {
        int k = idx >> 4, rr = idx & 15, qq = rr >> 2, g = rr & 3;
        sW[idx] = Wr[(size_t)k * G4_ + g * U_ + u0 + qq];
    }

    float c = 0.f;
    float* h0 = &g_h[dir][0][0];
    float* h1 = &g_h[dir][1][0];
    __syncthreads();

    for (int t = 0; t < T_; t++) {
        const float* hr = ((t + 1) & 1) ? h1 : h0;
        for (int idx = tid * 4; idx < B_ * U_; idx += 1024) {
            float4 v = __ldcg((const float4*)(hr + idx));
            int row = idx >> 8, col = idx & 255;
            *(float4*)&sH[row * 260 + col] = v;
        }
        __syncthreads();

        const float* p = pre + ((size_t)t * B_ + b) * G4_ + u;
        float z0 = p[0], z1 = p[U_], z2 = p[2 * U_], z3 = p[3 * U_];
        const float* hrow = &sH[b * 260];
#pragma unroll 8
        for (int k = 0; k < U_; k++) {
            float hv = hrow[k];
            float4 w = *(const float4*)&sW[k * 16 + q * 4];
            z0 += hv * w.x;
            z1 += hv * w.y;
            z2 += hv * w.z;
            z3 += hv * w.w;
        }
        float ig = 1.f / (1.f + __expf(-z0));
        float fg = 1.f / (1.f + __expf(-z1));
        float gg = tanhf(z2);
        float og = 1.f / (1.f + __expf(-z3));
        c = fg * c + ig * gg;
        float h = og * tanhf(c);

        float* hw = (t & 1) ? h1 : h0;
        hw[b * U_ + u] = h;
        int tout = dir ? (T_ - 1 - t) : t;
        out[((size_t)b * T_ + tout) * (2 * U_) + dir * U_ + u] = h;

        __syncthreads();
        if (tid == 0) {
            __threadfence();
            atomicAdd(bar, 1u);
            unsigned target = (unsigned)(t + 1) * RNN_CTAS;
            unsigned v;
            do {
                asm volatile("ld.global.acquire.gpu.u32 %0, [%1];" : "=r"(v) : "l"(bar));
            } while (v < target);
        }
        __syncthreads();
    }
}

// ---------------- launcher ----------------
extern "C" void kernel_launch(void* const* d_in, const int* in_sizes, int n_in,
                              void* d_out, int out_size)
{
    const float* inputs = (const float*)d_in[0];
    const float* convk  = (const float*)d_in[1];
    const float* convb  = (const float*)d_in[2];
    const float* bng    = (const float*)d_in[3];
    const float* bnb    = (const float*)d_in[4];
    const float* bnm    = (const float*)d_in[5];
    const float* bnv    = (const float*)d_in[6];
    const float* wk_f   = (const float*)d_in[7];
    const float* wr_f   = (const float*)d_in[8];
    const float* bi_f   = (const float*)d_in[9];
    const float* wk_b   = (const float*)d_in[10];
    const float* wr_b   = (const float*)d_in[11];
    const float* bi_b   = (const float*)d_in[12];
    float* out = (float*)d_out;

    uint16_t *xh0, *xl0, *xh1, *xl1, *wch, *wcl, *wlh, *wll;
    float *pre_f, *pre_b;
    cudaGetSymbolAddress((void**)&xh0, g_xh0);
    cudaGetSymbolAddress((void**)&xl0, g_xl0);
    cudaGetSymbolAddress((void**)&xh1, g_xh1);
    cudaGetSymbolAddress((void**)&xl1, g_xl1);
    cudaGetSymbolAddress((void**)&wch, g_wch);
    cudaGetSymbolAddress((void**)&wcl, g_wcl);
    cudaGetSymbolAddress((void**)&wlh, g_wlh);
    cudaGetSymbolAddress((void**)&wll, g_wll);
    cudaGetSymbolAddress((void**)&pre_f, g_pre_f);
    cudaGetSymbolAddress((void**)&pre_b, g_pre_b);

    cudaFuncSetAttribute(mma_gemm<0>, cudaFuncAttributeMaxDynamicSharedMemorySize, GSMEM);
    cudaFuncSetAttribute(mma_gemm<1>, cudaFuncAttributeMaxDynamicSharedMemorySize, GSMEM);
    cudaFuncSetAttribute(mma_gemm<2>, cudaFuncAttributeMaxDynamicSharedMemorySize, GSMEM);

    init_kernel<<<512, 256>>>();
    pad_pack<<<8192, 256>>>(inputs);
    wprep<<<8192, 256>>>(convk, wk_f, wk_b);

    const size_t wcs = (size_t)512 * 2560;
    dim3 gc(D_ / BN, T_ / BM, B_);           // (4, 8, 64)
    mma_gemm<0><<<gc, 256, GSMEM>>>(xh0, xl0, wch + 0 * wcs, wcl + 0 * wcs, KTAP * D_,
                                    convb + 0 * D_, bng + 0 * D_, bnb + 0 * D_,
                                    bnm + 0 * D_, bnv + 0 * D_, xh1, xl1, nullptr);
    mma_gemm<0><<<gc, 256, GSMEM>>>(xh1, xl1, wch + 1 * wcs, wcl + 1 * wcs, KTAP * D_,
                                    convb + 1 * D_, bng + 1 * D_, bnb + 1 * D_,
                                    bnm + 1 * D_, bnv + 1 * D_, xh0, xl0, nullptr);
    mma_gemm<0><<<gc, 256, GSMEM>>>(xh0, xl0, wch + 2 * wcs, wcl + 2 * wcs, KTAP * D_,
                                    convb + 2 * D_, bng + 2 * D_, bnb + 2 * D_,
                                    bnm + 2 * D_, bnv + 2 * D_, xh1, xl1, nullptr);

    const size_t wls = (size_t)1024 * 512;
    dim3 gl(G4_ / BN, T_ / BM, B_);          // (8, 8, 64)
    mma_gemm<1><<<gl, 256, GSMEM>>>(xh1 + 2 * D_, xl1 + 2 * D_, wlh + 0 * wls, wll + 0 * wls, D_,
                                    bi_f, bng, bnb, bnm, bnv, nullptr, nullptr, pre_f);
    mma_gemm<2><<<gl, 256, GSMEM>>>(xh1 + 2 * D_, xl1 + 2 * D_, wlh + 1 * wls, wll + 1 * wls, D_,
                                    bi_b, bng, bnb, bnm, bnv, nullptr, nullptr, pre_b);

    const int lstm_smem = (4096 + 64 * 260) * (int)sizeof(float);
    cudaFuncSetAttribute(lstm_kernel, cudaFuncAttributeMaxDynamicSharedMemorySize, lstm_smem);
    lstm_kernel<<<2 * RNN_CTAS, 256, lstm_smem>>>(pre_f, pre_b, wr_f, wr_b, out);
}

// round 7
// speedup vs baseline: 1.7813x; 1.1313x over previous
#include <cuda_runtime.h>
#include <cuda_bf16.h>
#include <cstdint>
#include <math.h>

#define B_    64
#define T_    1024
#define D_    512
#define KTAP  5
#define U_    256
#define G4_   1024
#define TP_   (T_ + 4)
#define XPD_  (TP_ * D_)
#define RNN_CTAS 64

#define BM    128
#define BN    128
#define KC    32                 // bf16 k per chunk
#define ROWB  80                 // smem row stride (bytes) -> conflict-free ldmatrix
#define TILEB (128 * ROWB)       // 10240 B per tile
#define STAGEB (4 * TILEB)       // AH, AL, BH, BL
#define NSTG  2
#define GSMEM (NSTG * STAGEB)    // 80 KB -> 2 CTAs/SM

// ---------------- scratch: separate hi/lo bf16 planes ----------------
__device__ uint16_t g_xh0[(size_t)B_ * XPD_];
__device__ uint16_t g_xl0[(size_t)B_ * XPD_];
__device__ uint16_t g_xh1[(size_t)B_ * XPD_];
__device__ uint16_t g_xl1[(size_t)B_ * XPD_];
__device__ uint16_t g_wch[(size_t)3 * 512 * 2560];  // conv weights [i][n][kk]
__device__ uint16_t g_wcl[(size_t)3 * 512 * 2560];
__device__ uint16_t g_wlh[(size_t)2 * 1024 * 512];  // lstm kernels [dir][n][d]
__device__ uint16_t g_wll[(size_t)2 * 1024 * 512];
__device__ float    g_pre_f[(size_t)T_ * B_ * G4_];
__device__ float    g_pre_b[(size_t)T_ * B_ * G4_];
__device__ float    g_h[2][2][B_ * U_];
__device__ unsigned g_bar[2];

// ---------------- helpers ----------------
__device__ __forceinline__ uint32_t smem_u32(const void* p) {
    uint32_t a;
    asm("{ .reg .u64 t; cvta.to.shared.u64 t, %1; cvt.u32.u64 %0, t; }" : "=r"(a) : "l"(p));
    return a;
}
__device__ __forceinline__ void split_hl(float v, uint16_t& h, uint16_t& l) {
    __nv_bfloat16 bh = __float2bfloat16(v);
    float hf = __bfloat162float(bh);
    __nv_bfloat16 bl = __float2bfloat16(v - hf);
    h = __bfloat16_as_ushort(bh);
    l = __bfloat16_as_ushort(bl);
}
#define CP16(dst, src) \
    asm volatile("cp.async.cg.shared.global [%0], [%1], 16;" :: "r"(dst), "l"(src))
#define CP_COMMIT() asm volatile("cp.async.commit_group;" ::: "memory")
#define CP_WAIT(N)  asm volatile("cp.async.wait_group %0;" :: "n"(N) : "memory")
#define LDM_X4(R0, R1, R2, R3, ADDR)                                            \
    asm volatile("ldmatrix.sync.aligned.m8n8.x4.shared.b16 {%0,%1,%2,%3}, [%4];"\
        : "=r"(R0), "=r"(R1), "=r"(R2), "=r"(R3) : "r"(ADDR))
__device__ __forceinline__ void mma_bf16(float* c, const uint32_t* a, const uint32_t* b) {
    asm volatile(
        "mma.sync.aligned.m16n8k16.row.col.f32.bf16.bf16.f32 "
        "{%0,%1,%2,%3}, {%4,%5,%6,%7}, {%8,%9}, {%0,%1,%2,%3};"
        : "+f"(c[0]), "+f"(c[1]), "+f"(c[2]), "+f"(c[3])
        : "r"(a[0]), "r"(a[1]), "r"(a[2]), "r"(a[3]), "r"(b[0]), "r"(b[1]));
}
// packed fp32x2 (Blackwell): lanewise fma on b64 pairs
#define PACK2(d, lo, hi) asm("mov.b64 %0, {%1, %2};" : "=l"(d) : "f"(lo), "f"(hi))
#define UNPACK2(lo, hi, s) asm("mov.b64 {%0, %1}, %2;" : "=f"(lo), "=f"(hi) : "l"(s))
#define FMA2(d, a, b) asm("fma.rn.f32x2 %0, %1, %2, %0;" : "+l"(d) : "l"(a), "l"(b))

// ---------------- init ----------------
__global__ void init_kernel() {
    int idx = blockIdx.x * blockDim.x + threadIdx.x;
    int nh = B_ * 4 * D_;
    if (idx < nh) {
        int b = idx / (4 * D_);
        int r = (idx / D_) & 3;
        int d = idx % D_;
        int row = (r < 2) ? r : (TP_ - 4 + r);
        size_t o = (size_t)b * XPD_ + (size_t)row * D_ + d;
        g_xh0[o] = 0; g_xl0[o] = 0; g_xh1[o] = 0; g_xl1[o] = 0;
    }
    if (idx < 2 * 2 * B_ * U_) ((float*)g_h)[idx] = 0.f;
    if (idx < 2) g_bar[idx] = 0u;
}

// ---------------- pack input ----------------
__global__ void pad_pack(const float* __restrict__ in) {
    size_t total = (size_t)B_ * T_ * D_;
    for (size_t idx = (size_t)blockIdx.x * blockDim.x + threadIdx.x;
         idx < total; idx += (size_t)gridDim.x * blockDim.x) {
        size_t b = idx / ((size_t)T_ * D_);
        size_t r = idx % ((size_t)T_ * D_);
        size_t t = r / D_, d = r % D_;
        size_t o = b * XPD_ + (t + 2) * D_ + d;
        uint16_t h, l;
        split_hl(in[idx], h, l);
        g_xh0[o] = h; g_xl0[o] = l;
    }
}

// ---------------- transpose + split weights ----------------
__global__ void wprep(const float* __restrict__ convk,
                      const float* __restrict__ wkf, const float* __restrict__ wkb) {
    const size_t CONVN = (size_t)3 * 512 * 2560;
    const size_t LSTMN = (size_t)1024 * 512;
    size_t total = CONVN + 2 * LSTMN;
    for (size_t idx = (size_t)blockIdx.x * blockDim.x + threadIdx.x;
         idx < total; idx += (size_t)gridDim.x * blockDim.x) {
        uint16_t h, l;
        if (idx < CONVN) {
            size_t i = idx / ((size_t)512 * 2560);
            size_t r = idx % ((size_t)512 * 2560);
            size_t n = r / 2560, kk = r % 2560;
            size_t tap = kk >> 9, din = kk & 511;
            split_hl(convk[(((i * KTAP + tap) * D_) + din) * D_ + n], h, l);
            g_wch[idx] = h; g_wcl[idx] = l;
        } else if (idx < CONVN + LSTMN) {
            size_t j = idx - CONVN;
            size_t n = j >> 9, d = j & 511;
            split_hl(wkf[d * G4_ + n], h, l);
            g_wlh[j] = h; g_wll[j] = l;
        } else {
            size_t j = idx - CONVN - LSTMN;
            size_t n = j >> 9, d = j & 511;
            split_hl(wkb[d * G4_ + n], h, l);
            g_wlh[LSTMN + j] = h; g_wll[LSTMN + j] = l;
        }
    }
}

// ---------------- cp.async pipelined warp-MMA split-bf16 GEMM, 2 CTAs/SM ----------------
// MODE 0: conv (bias, BN, ReLU) -> hi/lo plane interior
// MODE 1/2: lstm pre (+bias) -> fp32 [(t or T-1-t)*B + b][G4]
template <int MODE>
__global__ __launch_bounds__(256, 2) void mma_gemm(
    const uint16_t* __restrict__ Ah, const uint16_t* __restrict__ Al,
    const uint16_t* __restrict__ Bh, const uint16_t* __restrict__ Bl,
    int KKtot,
    const float* __restrict__ bias,
    const float* __restrict__ bng, const float* __restrict__ bnb,
    const float* __restrict__ bnm, const float* __restrict__ bnv,
    uint16_t* __restrict__ Ch, uint16_t* __restrict__ Cl,
    float* __restrict__ Cf)
{
    extern __shared__ char smraw[];
    const uint32_t sbase = smem_u32(smraw);

    const int tid = threadIdx.x;
    const int wid = tid >> 5, lane = tid & 31;
    const int bz = blockIdx.z;
    const int t0 = blockIdx.y * BM;
    const int n0 = blockIdx.x * BN;
    const int wm = wid & 1;      // row group: wm*64
    const int wn = wid >> 1;     // col group: wn*32

    const uint32_t a_off = (uint32_t)((wm * 64 + (lane & 15)) * ROWB + (lane >> 4) * 16);
    const uint32_t b_off = (uint32_t)((wn * 32 + (lane & 7) + ((lane >> 4) << 3)) * ROWB
                                      + ((lane >> 3) & 1) * 16);

    const uint16_t* Ahb = Ah + (size_t)bz * XPD_;
    const uint16_t* Alb = Al + (size_t)bz * XPD_;
    const int NCH = KKtot / KC;

    float cacc[4][4][4];
#pragma unroll
    for (int i = 0; i < 4; i++)
#pragma unroll
        for (int j = 0; j < 4; j++)
#pragma unroll
            for (int q = 0; q < 4; q++) cacc[i][j][q] = 0.f;

    auto issue = [&](int cc) {
        const int st = cc & 1;
        const int kk0 = cc * KC;
        const int tap = kk0 >> 9;
        const int d0 = kk0 & 511;
        const uint32_t sb = sbase + st * STAGEB;
#pragma unroll
        for (int half = 0; half < 2; half++) {
            const int s = tid + half * 256;
            const int row = s >> 2, seg = s & 3;
            const uint32_t doff = (uint32_t)(row * ROWB + seg * 16);
            const size_t aoff = (size_t)(t0 + row + tap) * D_ + d0 + seg * 8;
            const size_t boff = (size_t)(n0 + row) * KKtot + kk0 + seg * 8;
            CP16(sb + doff,             Ahb + aoff);
            CP16(sb + TILEB + doff,     Alb + aoff);
            CP16(sb + 2 * TILEB + doff, Bh + boff);
            CP16(sb + 3 * TILEB + doff, Bl + boff);
        }
        CP_COMMIT();
    };

    auto compute = [&](int st) {
        const uint32_t SB = sbase + st * STAGEB;
#pragma unroll
        for (int k16 = 0; k16 < 2; k16++) {
            const uint32_t kof = k16 * 32;
            uint32_t bh[4][2], bl[4][2];
#pragma unroll
            for (int nfp = 0; nfp < 2; nfp++) {
                uint32_t bd = SB + 2 * TILEB + b_off + nfp * (16 * ROWB) + kof;
                LDM_X4(bh[2 * nfp][0], bh[2 * nfp][1], bh[2 * nfp + 1][0], bh[2 * nfp + 1][1], bd);
                LDM_X4(bl[2 * nfp][0], bl[2 * nfp][1], bl[2 * nfp + 1][0], bl[2 * nfp + 1][1], bd + TILEB);
            }
#pragma unroll
            for (int mf = 0; mf < 4; mf++) {
                uint32_t ah[4], al[4];
                uint32_t ad = SB + a_off + mf * (16 * ROWB) + kof;
                LDM_X4(ah[0], ah[1], ah[2], ah[3], ad);
                LDM_X4(al[0], al[1], al[2], al[3], ad + TILEB);
#pragma unroll
                for (int nf = 0; nf < 4; nf++) {
                    mma_bf16(cacc[mf][nf], ah, bh[nf]);
                    mma_bf16(cacc[mf][nf], al, bh[nf]);
                    mma_bf16(cacc[mf][nf], ah, bl[nf]);
                }
            }
        }
    };

    issue(0);
    if (NCH > 1) issue(1);

    for (int cc = 0; cc < NCH; cc++) {
        CP_WAIT(1);
        __syncthreads();
        compute(cc & 1);
        __syncthreads();
        if (cc + 2 < NCH) issue(cc + 2);
    }

    // ---------------- epilogue ----------------
    const int r0 = lane >> 2;
    const int cq = (lane & 3) * 2;
    float mul0[4], mul1[4], add0[4], add1[4];
#pragma unroll
    for (int nf = 0; nf < 4; nf++) {
        int n = n0 + wn * 32 + nf * 8 + cq;
        float b0 = __ldg(&bias[n]), b1 = __ldg(&bias[n + 1]);
        if (MODE == 0) {
            float s0 = __ldg(&bng[n]) * rsqrtf(__ldg(&bnv[n]) + 1e-3f);
            float s1 = __ldg(&bng[n + 1]) * rsqrtf(__ldg(&bnv[n + 1]) + 1e-3f);
            mul0[nf] = s0; mul1[nf] = s1;
            add0[nf] = s0 * (b0 - __ldg(&bnm[n])) + __ldg(&bnb[n]);
            add1[nf] = s1 * (b1 - __ldg(&bnm[n + 1])) + __ldg(&bnb[n + 1]);
        } else {
            mul0[nf] = 1.f; mul1[nf] = 1.f;
            add0[nf] = b0;  add1[nf] = b1;
        }
    }

#pragma unroll
    for (int mf = 0; mf < 4; mf++) {
#pragma unroll
        for (int half = 0; half < 2; half++) {
            int m = wm * 64 + mf * 16 + r0 + half * 8;
#pragma unroll
            for (int nf = 0; nf < 4; nf++) {
                float v0 = fmaf(cacc[mf][nf][2 * half + 0], mul0[nf], add0[nf]);
                float v1 = fmaf(cacc[mf][nf][2 * half + 1], mul1[nf], add1[nf]);
                int nc = n0 + wn * 32 + nf * 8 + cq;
                if (MODE == 0) {
                    v0 = fmaxf(v0, 0.f);
                    v1 = fmaxf(v1, 0.f);
                    uint16_t h0, l0, h1, l1;
                    split_hl(v0, h0, l0);
                    split_hl(v1, h1, l1);
                    size_t off = (size_t)bz * XPD_ + (size_t)(t0 + m + 2) * D_ + nc;
                    *(uint32_t*)(Ch + off) = (uint32_t)h0 | ((uint32_t)h1 << 16);
                    *(uint32_t*)(Cl + off) = (uint32_t)l0 | ((uint32_t)l1 << 16);
                } else {
                    int t = t0 + m;
                    size_t off = (MODE == 1)
                        ? ((size_t)t * B_ + bz) * G4_ + nc
                        : ((size_t)(T_ - 1 - t) * B_ + bz) * G4_ + nc;
                    *(float2*)(Cf + off) = make_float2(v0, v1);
                }
            }
        }
    }
}

// ---------------- persistent bi-LSTM recurrence: packed f32x2 gate GEMV ----------------
// sW layout: [k2:128][qq:4][g:4][par:2] floats = 16 uint64 per k2.
// Thread (b,q): gate pairs at uint64 index k2*16 + q*4 + g.
__global__ __launch_bounds__(256) void lstm_kernel(
    const float* __restrict__ pre_f, const float* __restrict__ pre_b,
    const float* __restrict__ wr_f,  const float* __restrict__ wr_b,
    float* __restrict__ out)
{
    extern __shared__ float sm[];
    float* sW = sm;            // [128][4][4][2] = 4096 floats
    float* sH = sm + 4096;     // [64][260]

    const int bx  = blockIdx.x;
    const int dir = bx >> 6;
    const int u0  = (bx & 63) << 2;
    const float* pre = dir ? pre_b : pre_f;
    const float* Wr  = dir ? wr_b  : wr_f;
    unsigned* bar = &g_bar[dir];

    const int tid = threadIdx.x;
    const int b = tid >> 2, q = tid & 3, u = u0 + q;

    // fill sW in the paired layout: idx = k2*32 + qq*8 + g*2 + par, k = 2*k2 + par
    for (int idx = tid; idx < 4096; idx += 256) {
        int par = idx & 1;
        int rest = idx >> 1;
        int g = rest & 3, qq = (rest >> 2) & 3, k2 = rest >> 4;
        int k = 2 * k2 + par;
        sW[idx] = Wr[(size_t)k * G4_ + g * U_ + u0 + qq];
    }

    float c = 0.f;
    float* h0 = &g_h[dir][0][0];
    float* h1 = &g_h[dir][1][0];
    __syncthreads();

    const uint64_t* wbase = (const uint64_t*)(sW) + q * 4;   // gate pairs for this q

    for (int t = 0; t < T_; t++) {
        // prefetch pre-activations (independent of h staging)
        const float* p = pre + ((size_t)t * B_ + b) * G4_ + u;
        float z0 = __ldg(&p[0]);
        float z1 = __ldg(&p[U_]);
        float z2 = __ldg(&p[2 * U_]);
        float z3 = __ldg(&p[3 * U_]);

        const float* hr = ((t + 1) & 1) ? h1 : h0;
        for (int idx = tid * 4; idx < B_ * U_; idx += 1024) {
            float4 v = __ldcg((const float4*)(hr + idx));
            int row = idx >> 8, col = idx & 255;
            *(float4*)&sH[row * 260 + col] = v;
        }
        __syncthreads();

        uint64_t ai, af, ag, ao;
        PACK2(ai, z0, 0.f);
        PACK2(af, z1, 0.f);
        PACK2(ag, z2, 0.f);
        PACK2(ao, z3, 0.f);

        const float* hrow = &sH[b * 260];
#pragma unroll 8
        for (int k2 = 0; k2 < U_ / 2; k2++) {
            uint64_t h2 = *(const uint64_t*)(hrow + k2 * 2);
            const uint64_t* wp = wbase + k2 * 16;      // 16 uint64 per k2 block
            FMA2(ai, h2, wp[0]);
            FMA2(af, h2, wp[1]);
            FMA2(ag, h2, wp[2]);
            FMA2(ao, h2, wp[3]);
        }
        float e0, e1;
        UNPACK2(e0, e1, ai); z0 = e0 + e1;
        UNPACK2(e0, e1, af); z1 = e0 + e1;
        UNPACK2(e0, e1, ag); z2 = e0 + e1;
        UNPACK2(e0, e1, ao); z3 = e0 + e1;

        float ig = 1.f / (1.f + __expf(-z0));
        float fg = 1.f / (1.f + __expf(-z1));
        float gg = tanhf(z2);
        float og = 1.f / (1.f + __expf(-z3));
        c = fg * c + ig * gg;
        float h = og * tanhf(c);

        float* hw = (t & 1) ? h1 : h0;
        hw[b * U_ + u] = h;
        int tout = dir ? (T_ - 1 - t) : t;
        out[((size_t)b * T_ + tout) * (2 * U_) + dir * U_ + u] = h;

        __syncthreads();
        if (tid == 0) {
            __threadfence();
            atomicAdd(bar, 1u);
            unsigned target = (unsigned)(t + 1) * RNN_CTAS;
            unsigned v;
            do {
                asm volatile("ld.global.acquire.gpu.u32 %0, [%1];" : "=r"(v) : "l"(bar));
            } while (v < target);
        }
        __syncthreads();
    }
}

// ---------------- launcher ----------------
extern "C" void kernel_launch(void* const* d_in, const int* in_sizes, int n_in,
                              void* d_out, int out_size)
{
    const float* inputs = (const float*)d_in[0];
    const float* convk  = (const float*)d_in[1];
    const float* convb  = (const float*)d_in[2];
    const float* bng    = (const float*)d_in[3];
    const float* bnb    = (const float*)d_in[4];
    const float* bnm    = (const float*)d_in[5];
    const float* bnv    = (const float*)d_in[6];
    const float* wk_f   = (const float*)d_in[7];
    const float* wr_f   = (const float*)d_in[8];
    const float* bi_f   = (const float*)d_in[9];
    const float* wk_b   = (const float*)d_in[10];
    const float* wr_b   = (const float*)d_in[11];
    const float* bi_b   = (const float*)d_in[12];
    float* out = (float*)d_out;

    uint16_t *xh0, *xl0, *xh1, *xl1, *wch, *wcl, *wlh, *wll;
    float *pre_f, *pre_b;
    cudaGetSymbolAddress((void**)&xh0, g_xh0);
    cudaGetSymbolAddress((void**)&xl0, g_xl0);
    cudaGetSymbolAddress((void**)&xh1, g_xh1);
    cudaGetSymbolAddress((void**)&xl1, g_xl1);
    cudaGetSymbolAddress((void**)&wch, g_wch);
    cudaGetSymbolAddress((void**)&wcl, g_wcl);
    cudaGetSymbolAddress((void**)&wlh, g_wlh);
    cudaGetSymbolAddress((void**)&wll, g_wll);
    cudaGetSymbolAddress((void**)&pre_f, g_pre_f);
    cudaGetSymbolAddress((void**)&pre_b, g_pre_b);

    cudaFuncSetAttribute(mma_gemm<0>, cudaFuncAttributeMaxDynamicSharedMemorySize, GSMEM);
    cudaFuncSetAttribute(mma_gemm<1>, cudaFuncAttributeMaxDynamicSharedMemorySize, GSMEM);
    cudaFuncSetAttribute(mma_gemm<2>, cudaFuncAttributeMaxDynamicSharedMemorySize, GSMEM);

    init_kernel<<<512, 256>>>();
    pad_pack<<<8192, 256>>>(inputs);
    wprep<<<8192, 256>>>(convk, wk_f, wk_b);

    const size_t wcs = (size_t)512 * 2560;
    dim3 gc(D_ / BN, T_ / BM, B_);           // (4, 8, 64)
    mma_gemm<0><<<gc, 256, GSMEM>>>(xh0, xl0, wch + 0 * wcs, wcl + 0 * wcs, KTAP * D_,
                                    convb + 0 * D_, bng + 0 * D_, bnb + 0 * D_,
                                    bnm + 0 * D_, bnv + 0 * D_, xh1, xl1, nullptr);
    mma_gemm<0><<<gc, 256, GSMEM>>>(xh1, xl1, wch + 1 * wcs, wcl + 1 * wcs, KTAP * D_,
                                    convb + 1 * D_, bng + 1 * D_, bnb + 1 * D_,
                                    bnm + 1 * D_, bnv + 1 * D_, xh0, xl0, nullptr);
    mma_gemm<0><<<gc, 256, GSMEM>>>(xh0, xl0, wch + 2 * wcs, wcl + 2 * wcs, KTAP * D_,
                                    convb + 2 * D_, bng + 2 * D_, bnb + 2 * D_,
                                    bnm + 2 * D_, bnv + 2 * D_, xh1, xl1, nullptr);

    const size_t wls = (size_t)1024 * 512;
    dim3 gl(G4_ / BN, T_ / BM, B_);          // (8, 8, 64)
    mma_gemm<1><<<gl, 256, GSMEM>>>(xh1 + 2 * D_, xl1 + 2 * D_, wlh + 0 * wls, wll + 0 * wls, D_,
                                    bi_f, bng, bnb, bnm, bnv, nullptr, nullptr, pre_f);
    mma_gemm<2><<<gl, 256, GSMEM>>>(xh1 + 2 * D_, xl1 + 2 * D_, wlh + 1 * wls, wll + 1 * wls, D_,
                                    bi_b, bng, bnb, bnm, bnv, nullptr, nullptr, pre_b);

    const int lstm_smem = (4096 + 64 * 260) * (int)sizeof(float);
    cudaFuncSetAttribute(lstm_kernel, cudaFuncAttributeMaxDynamicSharedMemorySize, lstm_smem);
    lstm_kernel<<<2 * RNN_CTAS, 256, lstm_smem>>>(pre_f, pre_b, wr_f, wr_b, out);
}

// round 8
// speedup vs baseline: 2.0371x; 1.1436x over previous
#include <cuda_runtime.h>
#include <cuda_fp16.h>
#include <cstdint>
#include <math.h>

#define B_    64
#define T_    1024
#define D_    512
#define KTAP  5
#define U_    256
#define G4_   1024
#define TP_   (T_ + 4)
#define XPD_  (TP_ * D_)
#define RNN_CTAS 64

#define BM    128
#define BN    128
#define KC    32                 // fp16 k per chunk
#define ROWB  80                 // smem row stride (bytes) -> conflict-free ldmatrix
#define TILEB (128 * ROWB)       // 10240 B per tile
#define STAGEB (3 * TILEB)       // A, BH, BL
#define NSTG  3
#define GSMEM (NSTG * STAGEB)    // 90 KB -> 2 CTAs/SM

// ---------------- scratch ----------------
__device__ uint16_t g_x0[(size_t)B_ * XPD_];        // fp16 activation planes
__device__ uint16_t g_x1[(size_t)B_ * XPD_];
__device__ uint16_t g_wch[(size_t)3 * 512 * 2560];  // conv weights hi [i][n][kk]
__device__ uint16_t g_wcl[(size_t)3 * 512 * 2560];  // conv weights lo
__device__ uint16_t g_wlh[(size_t)2 * 1024 * 512];  // lstm kernels hi [dir][n][d]
__device__ uint16_t g_wll[(size_t)2 * 1024 * 512];  // lstm kernels lo
__device__ float    g_pre_f[(size_t)T_ * B_ * G4_];
__device__ float    g_pre_b[(size_t)T_ * B_ * G4_];
__device__ float    g_h[2][2][B_ * U_];
__device__ unsigned g_bar[2];

// ---------------- helpers ----------------
__device__ __forceinline__ uint32_t smem_u32(const void* p) {
    uint32_t a;
    asm("{ .reg .u64 t; cvta.to.shared.u64 t, %1; cvt.u32.u64 %0, t; }" : "=r"(a) : "l"(p));
    return a;
}
__device__ __forceinline__ uint16_t f2h(float v) {
    return __half_as_ushort(__float2half(v));
}
__device__ __forceinline__ void split_h16(float v, uint16_t& h, uint16_t& l) {
    __half hh = __float2half(v);
    float hf = __half2float(hh);
    h = __half_as_ushort(hh);
    l = __half_as_ushort(__float2half(v - hf));
}
#define CP16(dst, src) \
    asm volatile("cp.async.cg.shared.global [%0], [%1], 16;" :: "r"(dst), "l"(src))
#define CP_COMMIT() asm volatile("cp.async.commit_group;" ::: "memory")
#define CP_WAIT(N)  asm volatile("cp.async.wait_group %0;" :: "n"(N) : "memory")
#define LDM_X4(R0, R1, R2, R3, ADDR)                                            \
    asm volatile("ldmatrix.sync.aligned.m8n8.x4.shared.b16 {%0,%1,%2,%3}, [%4];"\
        : "=r"(R0), "=r"(R1), "=r"(R2), "=r"(R3) : "r"(ADDR))
__device__ __forceinline__ void mma_f16(float* c, const uint32_t* a, const uint32_t* b) {
    asm volatile(
        "mma.sync.aligned.m16n8k16.row.col.f32.f16.f16.f32 "
        "{%0,%1,%2,%3}, {%4,%5,%6,%7}, {%8,%9}, {%0,%1,%2,%3};"
        : "+f"(c[0]), "+f"(c[1]), "+f"(c[2]), "+f"(c[3])
        : "r"(a[0]), "r"(a[1]), "r"(a[2]), "r"(a[3]), "r"(b[0]), "r"(b[1]));
}
// packed fp32x2 (Blackwell)
#define PACK2(d, lo, hi) asm("mov.b64 %0, {%1, %2};" : "=l"(d) : "f"(lo), "f"(hi))
#define UNPACK2(lo, hi, s) asm("mov.b64 {%0, %1}, %2;" : "=f"(lo), "=f"(hi) : "l"(s))
#define FMA2(d, a, b) asm("fma.rn.f32x2 %0, %1, %2, %0;" : "+l"(d) : "l"(a), "l"(b))

// ---------------- init ----------------
__global__ void init_kernel() {
    int idx = blockIdx.x * blockDim.x + threadIdx.x;
    int nh = B_ * 4 * D_;
    if (idx < nh) {
        int b = idx / (4 * D_);
        int r = (idx / D_) & 3;
        int d = idx % D_;
        int row = (r < 2) ? r : (TP_ - 4 + r);
        size_t o = (size_t)b * XPD_ + (size_t)row * D_ + d;
        g_x0[o] = 0; g_x1[o] = 0;
    }
    if (idx < 2 * 2 * B_ * U_) ((float*)g_h)[idx] = 0.f;
    if (idx < 2) g_bar[idx] = 0u;
}

// ---------------- pack input (single fp16) ----------------
__global__ void pad_pack(const float* __restrict__ in) {
    size_t total = (size_t)B_ * T_ * D_;
    for (size_t idx = (size_t)blockIdx.x * blockDim.x + threadIdx.x;
         idx < total; idx += (size_t)gridDim.x * blockDim.x) {
        size_t b = idx / ((size_t)T_ * D_);
        size_t r = idx % ((size_t)T_ * D_);
        size_t t = r / D_, d = r % D_;
        g_x0[b * XPD_ + (t + 2) * D_ + d] = f2h(in[idx]);
    }
}

// ---------------- transpose + split weights (fp16 hi/lo) ----------------
__global__ void wprep(const float* __restrict__ convk,
                      const float* __restrict__ wkf, const float* __restrict__ wkb) {
    const size_t CONVN = (size_t)3 * 512 * 2560;
    const size_t LSTMN = (size_t)1024 * 512;
    size_t total = CONVN + 2 * LSTMN;
    for (size_t idx = (size_t)blockIdx.x * blockDim.x + threadIdx.x;
         idx < total; idx += (size_t)gridDim.x * blockDim.x) {
        uint16_t h, l;
        if (idx < CONVN) {
            size_t i = idx / ((size_t)512 * 2560);
            size_t r = idx % ((size_t)512 * 2560);
            size_t n = r / 2560, kk = r % 2560;
            size_t tap = kk >> 9, din = kk & 511;
            split_h16(convk[(((i * KTAP + tap) * D_) + din) * D_ + n], h, l);
            g_wch[idx] = h; g_wcl[idx] = l;
        } else if (idx < CONVN + LSTMN) {
            size_t j = idx - CONVN;
            size_t n = j >> 9, d = j & 511;
            split_h16(wkf[d * G4_ + n], h, l);
            g_wlh[j] = h; g_wll[j] = l;
        } else {
            size_t j = idx - CONVN - LSTMN;
            size_t n = j >> 9, d = j & 511;
            split_h16(wkb[d * G4_ + n], h, l);
            g_wlh[LSTMN + j] = h; g_wll[LSTMN + j] = l;
        }
    }
}

// ---------------- fp16 2-term warp-MMA GEMM (A single, B split hi/lo) ----------------
// 3-stage cp.async pipeline, ONE barrier per chunk, 2 CTAs/SM.
// MODE 0: conv (bias, BN, ReLU) -> fp16 plane interior
// MODE 1/2: lstm pre (+bias) -> fp32 [(t or T-1-t)*B + b][G4]
template <int MODE>
__global__ __launch_bounds__(256, 2) void mma_gemm(
    const uint16_t* __restrict__ Ap,
    const uint16_t* __restrict__ Bh, const uint16_t* __restrict__ Bl,
    int KKtot,
    const float* __restrict__ bias,
    const float* __restrict__ bng, const float* __restrict__ bnb,
    const float* __restrict__ bnm, const float* __restrict__ bnv,
    uint16_t* __restrict__ Cp, float* __restrict__ Cf)
{
    extern __shared__ char smraw[];
    const uint32_t sbase = smem_u32(smraw);

    const int tid = threadIdx.x;
    const int wid = tid >> 5, lane = tid & 31;
    const int bz = blockIdx.z;
    const int t0 = blockIdx.y * BM;
    const int n0 = blockIdx.x * BN;
    const int wm = wid & 1;      // row group: wm*64
    const int wn = wid >> 1;     // col group: wn*32

    const uint32_t a_off = (uint32_t)((wm * 64 + (lane & 15)) * ROWB + (lane >> 4) * 16);
    const uint32_t b_off = (uint32_t)((wn * 32 + (lane & 7) + ((lane >> 4) << 3)) * ROWB
                                      + ((lane >> 3) & 1) * 16);

    const uint16_t* Ab = Ap + (size_t)bz * XPD_;
    const int NCH = KKtot / KC;

    float cacc[4][4][4];
#pragma unroll
    for (int i = 0; i < 4; i++)
#pragma unroll
        for (int j = 0; j < 4; j++)
#pragma unroll
            for (int q = 0; q < 4; q++) cacc[i][j][q] = 0.f;

    auto issue = [&](int cc) {
        const int st = cc % NSTG;
        const int kk0 = cc * KC;
        const int tap = kk0 >> 9;
        const int d0 = kk0 & 511;
        const uint32_t sb = sbase + st * STAGEB;
#pragma unroll
        for (int half = 0; half < 2; half++) {
            const int s = tid + half * 256;
            const int row = s >> 2, seg = s & 3;
            const uint32_t doff = (uint32_t)(row * ROWB + seg * 16);
            const size_t aoff = (size_t)(t0 + row + tap) * D_ + d0 + seg * 8;
            const size_t boff = (size_t)(n0 + row) * KKtot + kk0 + seg * 8;
            CP16(sb + doff,             Ab + aoff);
            CP16(sb + TILEB + doff,     Bh + boff);
            CP16(sb + 2 * TILEB + doff, Bl + boff);
        }
        CP_COMMIT();
    };

    auto compute = [&](int st) {
        const uint32_t SB = sbase + st * STAGEB;
#pragma unroll
        for (int k16 = 0; k16 < 2; k16++) {
            const uint32_t kof = k16 * 32;
            uint32_t bh[4][2], bl[4][2];
#pragma unroll
            for (int nfp = 0; nfp < 2; nfp++) {
                uint32_t bd = SB + TILEB + b_off + nfp * (16 * ROWB) + kof;
                LDM_X4(bh[2 * nfp][0], bh[2 * nfp][1], bh[2 * nfp + 1][0], bh[2 * nfp + 1][1], bd);
                LDM_X4(bl[2 * nfp][0], bl[2 * nfp][1], bl[2 * nfp + 1][0], bl[2 * nfp + 1][1], bd + TILEB);
            }
#pragma unroll
            for (int mf = 0; mf < 4; mf++) {
                uint32_t af[4];
                uint32_t ad = SB + a_off + mf * (16 * ROWB) + kof;
                LDM_X4(af[0], af[1], af[2], af[3], ad);
#pragma unroll
                for (int nf = 0; nf < 4; nf++) {
                    mma_f16(cacc[mf][nf], af, bh[nf]);
                    mma_f16(cacc[mf][nf], af, bl[nf]);
                }
            }
        }
    };

    issue(0);
    issue(1);

    for (int cc = 0; cc < NCH; cc++) {
        CP_WAIT(1);
        __syncthreads();
        if (cc + 2 < NCH) issue(cc + 2);
        else CP_COMMIT();                 // empty group keeps wait-count aligned
        compute(cc % NSTG);
    }

    // ---------------- epilogue ----------------
    const int r0 = lane >> 2;
    const int cq = (lane & 3) * 2;
    float mul0[4], mul1[4], add0[4], add1[4];
#pragma unroll
    for (int nf = 0; nf < 4; nf++) {
        int n = n0 + wn * 32 + nf * 8 + cq;
        float b0 = __ldg(&bias[n]), b1 = __ldg(&bias[n + 1]);
        if (MODE == 0) {
            float s0 = __ldg(&bng[n]) * rsqrtf(__ldg(&bnv[n]) + 1e-3f);
            float s1 = __ldg(&bng[n + 1]) * rsqrtf(__ldg(&bnv[n + 1]) + 1e-3f);
            mul0[nf] = s0; mul1[nf] = s1;
            add0[nf] = s0 * (b0 - __ldg(&bnm[n])) + __ldg(&bnb[n]);
            add1[nf] = s1 * (b1 - __ldg(&bnm[n + 1])) + __ldg(&bnb[n + 1]);
        } else {
            mul0[nf] = 1.f; mul1[nf] = 1.f;
            add0[nf] = b0;  add1[nf] = b1;
        }
    }

#pragma unroll
    for (int mf = 0; mf < 4; mf++) {
#pragma unroll
        for (int half = 0; half < 2; half++) {
            int m = wm * 64 + mf * 16 + r0 + half * 8;
#pragma unroll
            for (int nf = 0; nf < 4; nf++) {
                float v0 = fmaf(cacc[mf][nf][2 * half + 0], mul0[nf], add0[nf]);
                float v1 = fmaf(cacc[mf][nf][2 * half + 1], mul1[nf], add1[nf]);
                int nc = n0 + wn * 32 + nf * 8 + cq;
                if (MODE == 0) {
                    v0 = fmaxf(v0, 0.f);
                    v1 = fmaxf(v1, 0.f);
                    size_t off = (size_t)bz * XPD_ + (size_t)(t0 + m + 2) * D_ + nc;
                    *(uint32_t*)(Cp + off) = (uint32_t)f2h(v0) | ((uint32_t)f2h(v1) << 16);
                } else {
                    int t = t0 + m;
                    size_t off = (MODE == 1)
                        ? ((size_t)t * B_ + bz) * G4_ + nc
                        : ((size_t)(T_ - 1 - t) * B_ + bz) * G4_ + nc;
                    *(float2*)(Cf + off) = make_float2(v0, v1);
                }
            }
        }
    }
}

// ---------------- persistent bi-LSTM recurrence: packed f32x2 gate GEMV ----------------
__global__ __launch_bounds__(256) void lstm_kernel(
    const float* __restrict__ pre_f, const float* __restrict__ pre_b,
    const float* __restrict__ wr_f,  const float* __restrict__ wr_b,
    float* __restrict__ out)
{
    extern __shared__ float sm[];
    float* sW = sm;            // [128][4][4][2] = 4096 floats
    float* sH = sm + 4096;     // [64][260]

    const int bx  = blockIdx.x;
    const int dir = bx >> 6;
    const int u0  = (bx & 63) << 2;
    const float* pre = dir ? pre_b : pre_f;
    const float* Wr  = dir ? wr_b  : wr_f;
    unsigned* bar = &g_bar[dir];

    const int tid = threadIdx.x;
    const int b = tid >> 2, q = tid & 3, u = u0 + q;

    for (int idx = tid; idx < 4096; idx += 256) {
        int par = idx & 1;
        int rest = idx >> 1;
        int g = rest & 3, qq = (rest >> 2) & 3, k2 = rest >> 4;
        int k = 2 * k2 + par;
        sW[idx] = Wr[(size_t)k * G4_ + g * U_ + u0 + qq];
    }

    float c = 0.f;
    float* h0 = &g_h[dir][0][0];
    float* h1 = &g_h[dir][1][0];
    __syncthreads();

    const uint64_t* wbase = (const uint64_t*)(sW) + q * 4;

    for (int t = 0; t < T_; t++) {
        const float* p = pre + ((size_t)t * B_ + b) * G4_ + u;
        float z0 = __ldg(&p[0]);
        float z1 = __ldg(&p[U_]);
        float z2 = __ldg(&p[2 * U_]);
        float z3 = __ldg(&p[3 * U_]);

        const float* hr = ((t + 1) & 1) ? h1 : h0;
        for (int idx = tid * 4; idx < B_ * U_; idx += 1024) {
            float4 v = __ldcg((const float4*)(hr + idx));
            int row = idx >> 8, col = idx & 255;
            *(float4*)&sH[row * 260 + col] = v;
        }
        __syncthreads();

        uint64_t ai, af, ag, ao;
        PACK2(ai, z0, 0.f);
        PACK2(af, z1, 0.f);
        PACK2(ag, z2, 0.f);
        PACK2(ao, z3, 0.f);

        const float* hrow = &sH[b * 260];
#pragma unroll 8
        for (int k2 = 0; k2 < U_ / 2; k2++) {
            uint64_t h2 = *(const uint64_t*)(hrow + k2 * 2);
            const uint64_t* wp = wbase + k2 * 16;
            FMA2(ai, h2, wp[0]);
            FMA2(af, h2, wp[1]);
            FMA2(ag, h2, wp[2]);
            FMA2(ao, h2, wp[3]);
        }
        float e0, e1;
        UNPACK2(e0, e1, ai); z0 = e0 + e1;
        UNPACK2(e0, e1, af); z1 = e0 + e1;
        UNPACK2(e0, e1, ag); z2 = e0 + e1;
        UNPACK2(e0, e1, ao); z3 = e0 + e1;

        float ig = 1.f / (1.f + __expf(-z0));
        float fg = 1.f / (1.f + __expf(-z1));
        float gg = tanhf(z2);
        float og = 1.f / (1.f + __expf(-z3));
        c = fg * c + ig * gg;
        float h = og * tanhf(c);

        float* hw = (t & 1) ? h1 : h0;
        hw[b * U_ + u] = h;
        int tout = dir ? (T_ - 1 - t) : t;
        out[((size_t)b * T_ + tout) * (2 * U_) + dir * U_ + u] = h;

        __syncthreads();
        if (tid == 0) {
            __threadfence();
            atomicAdd(bar, 1u);
            unsigned target = (unsigned)(t + 1) * RNN_CTAS;
            unsigned v;
            do {
                asm volatile("ld.global.acquire.gpu.u32 %0, [%1];" : "=r"(v) : "l"(bar));
            } while (v < target);
        }
        __syncthreads();
    }
}

// ---------------- launcher ----------------
extern "C" void kernel_launch(void* const* d_in, const int* in_sizes, int n_in,
                              void* d_out, int out_size)
{
    const float* inputs = (const float*)d_in[0];
    const float* convk  = (const float*)d_in[1];
    const float* convb  = (const float*)d_in[2];
    const float* bng    = (const float*)d_in[3];
    const float* bnb    = (const float*)d_in[4];
    const float* bnm    = (const float*)d_in[5];
    const float* bnv    = (const float*)d_in[6];
    const float* wk_f   = (const float*)d_in[7];
    const float* wr_f   = (const float*)d_in[8];
    const float* bi_f   = (const float*)d_in[9];
    const float* wk_b   = (const float*)d_in[10];
    const float* wr_b   = (const float*)d_in[11];
    const float* bi_b   = (const float*)d_in[12];
    float* out = (float*)d_out;

    uint16_t *x0, *x1, *wch, *wcl, *wlh, *wll;
    float *pre_f, *pre_b;
    cudaGetSymbolAddress((void**)&x0, g_x0);
    cudaGetSymbolAddress((void**)&x1, g_x1);
    cudaGetSymbolAddress((void**)&wch, g_wch);
    cudaGetSymbolAddress((void**)&wcl, g_wcl);
    cudaGetSymbolAddress((void**)&wlh, g_wlh);
    cudaGetSymbolAddress((void**)&wll, g_wll);
    cudaGetSymbolAddress((void**)&pre_f, g_pre_f);
    cudaGetSymbolAddress((void**)&pre_b, g_pre_b);

    cudaFuncSetAttribute(mma_gemm<0>, cudaFuncAttributeMaxDynamicSharedMemorySize, GSMEM);
    cudaFuncSetAttribute(mma_gemm<1>, cudaFuncAttributeMaxDynamicSharedMemorySize, GSMEM);
    cudaFuncSetAttribute(mma_gemm<2>, cudaFuncAttributeMaxDynamicSharedMemorySize, GSMEM);

    init_kernel<<<512, 256>>>();
    pad_pack<<<8192, 256>>>(inputs);
    wprep<<<8192, 256>>>(convk, wk_f, wk_b);

    const size_t wcs = (size_t)512 * 2560;
    dim3 gc(D_ / BN, T_ / BM, B_);           // (4, 8, 64)
    mma_gemm<0><<<gc, 256, GSMEM>>>(x0, wch + 0 * wcs, wcl + 0 * wcs, KTAP * D_,
                                    convb + 0 * D_, bng + 0 * D_, bnb + 0 * D_,
                                    bnm + 0 * D_, bnv + 0 * D_, x1, nullptr);
    mma_gemm<0><<<gc, 256, GSMEM>>>(x1, wch + 1 * wcs, wcl + 1 * wcs, KTAP * D_,
                                    convb + 1 * D_, bng + 1 * D_, bnb + 1 * D_,
                                    bnm + 1 * D_, bnv + 1 * D_, x0, nullptr);
    mma_gemm<0><<<gc, 256, GSMEM>>>(x0, wch + 2 * wcs, wcl + 2 * wcs, KTAP * D_,
                                    convb + 2 * D_, bng + 2 * D_, bnb + 2 * D_,
                                    bnm + 2 * D_, bnv + 2 * D_, x1, nullptr);

    const size_t wls = (size_t)1024 * 512;
    dim3 gl(G4_ / BN, T_ / BM, B_);          // (8, 8, 64)
    mma_gemm<1><<<gl, 256, GSMEM>>>(x1 + 2 * D_, wlh + 0 * wls, wll + 0 * wls, D_,
                                    bi_f, bng, bnb, bnm, bnv, nullptr, pre_f);
    mma_gemm<2><<<gl, 256, GSMEM>>>(x1 + 2 * D_, wlh + 1 * wls, wll + 1 * wls, D_,
                                    bi_b, bng, bnb, bnm, bnv, nullptr, pre_b);

    const int lstm_smem = (4096 + 64 * 260) * (int)sizeof(float);
    cudaFuncSetAttribute(lstm_kernel, cudaFuncAttributeMaxDynamicSharedMemorySize, lstm_smem);
    lstm_kernel<<<2 * RNN_CTAS, 256, lstm_smem>>>(pre_f, pre_b, wr_f, wr_b, out);
}